// round 15
// baseline (speedup 1.0000x reference)
#include <cuda_runtime.h>
#include <cuda_bf16.h>
#include <math.h>
#include <stdint.h>

// ===========================================================================
// Scratch (no allocations allowed)
// ===========================================================================
__device__ float g_magg[50048 * 64];
__device__ float g_wpart[148 * 64];
__device__ uint32_t g_zpk[50048 * 32];   // prepacked bf16x2 z_h

// ===========================================================================
// warp MMA m16n8k16 bf16 (sm_80+ PTX, no arch suffix)
// ===========================================================================
#define MMA_BF16(c, a0, a1, a2, a3, b0, b1) \
    asm volatile("mma.sync.aligned.m16n8k16.row.col.f32.bf16.bf16.f32 " \
        "{%0,%1,%2,%3},{%4,%5,%6,%7},{%8,%9},{%0,%1,%2,%3};" \
        : "+f"((c)[0]), "+f"((c)[1]), "+f"((c)[2]), "+f"((c)[3]) \
        : "r"(a0), "r"(a1), "r"(a2), "r"(a3), "r"(b0), "r"(b1))

__device__ __forceinline__ void red_add_v4(float* addr, float x, float y, float z, float w_) {
    asm volatile("red.global.add.v4.f32 [%0], {%1, %2, %3, %4};"
                 :: "l"(addr), "f"(x), "f"(y), "f"(z), "f"(w_) : "memory");
}

__device__ __forceinline__ uint32_t pack_hi(float v0, float v1) {
    return ((uint32_t)__bfloat16_as_ushort(__float2bfloat16(v1)) << 16) |
           (uint32_t)__bfloat16_as_ushort(__float2bfloat16(v0));
}

__device__ __forceinline__ void pack_pair(float v0, float v1, uint32_t& hi, uint32_t& lo) {
    __nv_bfloat16 h0 = __float2bfloat16(v0);
    __nv_bfloat16 h1 = __float2bfloat16(v1);
    float r0 = v0 - __bfloat162float(h0);
    float r1 = v1 - __bfloat162float(h1);
    hi = ((uint32_t)__bfloat16_as_ushort(h1) << 16) | (uint32_t)__bfloat16_as_ushort(h0);
    lo = ((uint32_t)__bfloat16_as_ushort(__float2bfloat16(r1)) << 16) |
         (uint32_t)__bfloat16_as_ushort(__float2bfloat16(r0));
}

__device__ __forceinline__ float bf_lo(uint32_t u) {
    return __bfloat162float(__ushort_as_bfloat16((unsigned short)(u & 0xffffu)));
}
__device__ __forceinline__ float bf_hi(uint32_t u) {
    return __bfloat162float(__ushort_as_bfloat16((unsigned short)(u >> 16)));
}

#define ASTR 76   // activation row stride, words (mod32=12, conflict-free)
#define WSTR 68   // weight row stride, words (mod32=4, conflict-free)

// ===========================================================================
// EDGE kernel: unchanged (measured best ~276us)
// ===========================================================================
#define ETHREADS 384
#define EWARPS   12

#define E_W1E   0
#define E_W1G   8704
#define E_W2    17408
#define E_ACT   21760
#define E_TGT   50944
#define E_GATE  51328
#define E_BE1   51712
#define E_BG1   51840
#define E_WG2   51968
#define E_BE2   52096
#define E_WORDS 52160
#define E_BYTES (E_WORDS * 4)

__global__ void __launch_bounds__(ETHREADS, 1)
edge_mma_kernel(const int* __restrict__ ei,
                const float* __restrict__ We1, const float* __restrict__ be1,
                const float* __restrict__ We2, const float* __restrict__ be2,
                const float* __restrict__ Wg1, const float* __restrict__ bg1,
                const float* __restrict__ Wg2, const float* __restrict__ bg2,
                int E) {
    extern __shared__ uint32_t smw[];
    float* smf = (float*)smw;
    int* smi = (int*)smw;
    uint16_t* smh = (uint16_t*)smw;

    const int t = threadIdx.x;
    const int w = t >> 5;
    const int l = t & 31;
    const int grp = l >> 2;
    const int qid = l & 3;

    for (int idx = t; idx < 136 * 128; idx += ETHREADS) {
        int k = idx >> 7, n = idx & 127;
        smh[(E_W1E + n * WSTR) * 2 + k] = __bfloat16_as_ushort(__float2bfloat16(We1[idx]));
        smh[(E_W1G + n * WSTR) * 2 + k] = __bfloat16_as_ushort(__float2bfloat16(Wg1[idx]));
    }
    for (int idx = t; idx < 128 * 64; idx += ETHREADS) {
        int k = idx >> 6, n = idx & 63;
        smh[(E_W2 + n * WSTR) * 2 + k] = __bfloat16_as_ushort(__float2bfloat16(We2[idx]));
    }
    if (t < 128) {
        smf[E_BE1 + t] = be1[t];
        smf[E_BG1 + t] = bg1[t];
        smf[E_WG2 + t] = Wg2[t];
    }
    if (t < 64) smf[E_BE2 + t] = be2[t];
    const float bg2v = __ldg(&bg2[0]);
    __syncthreads();

    const int nunits = (E + 31) / 32;
    const int bq = grp * WSTR + qid;
    const int e_local = w * 32 + l;
    uint32_t* const myrow = smw + E_ACT + e_local * ASTR;
    const int rowbase = (w * 32 + grp) * ASTR;
    const int row0 = w * 32 + grp;

    for (int unit = blockIdx.x * EWARPS + w; unit < nunits; unit += gridDim.x * EWARPS) {
        const int eg = unit * 32 + l;
        const int sN = (eg < E) ? ei[eg] : 0;
        const int tN = (eg < E) ? ei[E + eg] : 0;
        smi[E_TGT + e_local] = tN;
        const uint4* zs = (const uint4*)(g_zpk + (size_t)sN * 32);
        const uint4* zt = (const uint4*)(g_zpk + (size_t)tN * 32);
        uint4 s0 = zs[0];
        uint4 t0 = zt[0];
        myrow[0] = s0.x; myrow[1] = s0.y; myrow[2] = s0.z; myrow[3] = s0.w;
        myrow[32] = t0.x; myrow[33] = t0.y; myrow[34] = t0.z; myrow[35] = t0.w;
#pragma unroll
        for (int q = 1; q < 8; q++) {
            uint4 v = zs[q];
            myrow[4 * q] = v.x; myrow[4 * q + 1] = v.y;
            myrow[4 * q + 2] = v.z; myrow[4 * q + 3] = v.w;
        }
#pragma unroll
        for (int q = 1; q < 8; q++) {
            uint4 v = zt[q];
            myrow[32 + 4 * q] = v.x; myrow[33 + 4 * q] = v.y;
            myrow[34 + 4 * q] = v.z; myrow[35 + 4 * q] = v.w;
        }
        {
            float a0 = bf_lo(s0.x), a1 = bf_hi(s0.x), a2 = bf_lo(s0.y);
            float a3 = bf_hi(s0.y), a4 = bf_lo(s0.z), a5 = bf_hi(s0.z);
            float b0 = bf_lo(t0.x), b1 = bf_hi(t0.x), b2 = bf_lo(t0.y);
            float b3 = bf_hi(t0.y), b4 = bf_lo(t0.z), b5 = bf_hi(t0.z);
            float dx = a0 - b0, dy = a1 - b1, dz = a2 - b2;
            float dist = dx * dx + dy * dy + dz * dz;
            float cx = a4 * b5 - a5 * b4;
            float cy = a5 * b3 - a3 * b5;
            float cz = a3 * b4 - a4 * b3;
            float cn = sqrtf(cx * cx + cy * cy + cz * cz);
            myrow[64] = pack_hi(dx, dy);
            myrow[65] = pack_hi(dz, dist);
            myrow[66] = pack_hi(cx, cy);
            myrow[67] = pack_hi(cz, cn);
            myrow[68] = 0; myrow[69] = 0; myrow[70] = 0; myrow[71] = 0;
        }
        __syncwarp();

        uint32_t a1h[72];
        {
            const int r0w = rowbase + qid;
#pragma unroll
            for (int kt = 0; kt < 9; kt++) {
                int b0 = r0w + kt * 8;
                a1h[kt * 8 + 0] = smw[E_ACT + b0];
                a1h[kt * 8 + 1] = smw[E_ACT + b0 + 8 * ASTR];
                a1h[kt * 8 + 2] = smw[E_ACT + b0 + 4];
                a1h[kt * 8 + 3] = smw[E_ACT + b0 + 8 * ASTR + 4];
                a1h[kt * 8 + 4] = smw[E_ACT + b0 + 16 * ASTR];
                a1h[kt * 8 + 5] = smw[E_ACT + b0 + 24 * ASTR];
                a1h[kt * 8 + 6] = smw[E_ACT + b0 + 16 * ASTR + 4];
                a1h[kt * 8 + 7] = smw[E_ACT + b0 + 24 * ASTR + 4];
            }
        }
        __syncwarp();

#pragma unroll
        for (int nt = 0; nt < 16; nt++) {
            float c0[4] = {0.f, 0.f, 0.f, 0.f};
            float c1[4] = {0.f, 0.f, 0.f, 0.f};
            const int base = nt * 8 * WSTR + bq;
#pragma unroll
            for (int kt = 0; kt < 9; kt++) {
                int o = base + kt * 8;
                uint32_t b0 = smw[E_W1E + o], b1 = smw[E_W1E + o + 4];
                MMA_BF16(c0, a1h[kt*8+0], a1h[kt*8+1], a1h[kt*8+2], a1h[kt*8+3], b0, b1);
                MMA_BF16(c1, a1h[kt*8+4], a1h[kt*8+5], a1h[kt*8+6], a1h[kt*8+7], b0, b1);
            }
            const int n0 = nt * 8 + 2 * qid;
            const float be0 = smf[E_BE1 + n0], be1v = smf[E_BE1 + n0 + 1];
            const int wi = rowbase + nt * 4 + qid;
            smw[E_ACT + wi] =
                pack_hi(fmaxf(c0[0] + be0, 0.f), fmaxf(c0[1] + be1v, 0.f));
            smw[E_ACT + wi + 8 * ASTR] =
                pack_hi(fmaxf(c0[2] + be0, 0.f), fmaxf(c0[3] + be1v, 0.f));
            smw[E_ACT + wi + 16 * ASTR] =
                pack_hi(fmaxf(c1[0] + be0, 0.f), fmaxf(c1[1] + be1v, 0.f));
            smw[E_ACT + wi + 24 * ASTR] =
                pack_hi(fmaxf(c1[2] + be0, 0.f), fmaxf(c1[3] + be1v, 0.f));
        }

        float ps[4] = {0.f, 0.f, 0.f, 0.f};
#pragma unroll
        for (int nt = 0; nt < 16; nt++) {
            float c0[4] = {0.f, 0.f, 0.f, 0.f};
            float c1[4] = {0.f, 0.f, 0.f, 0.f};
            const int base = nt * 8 * WSTR + bq;
#pragma unroll
            for (int kt = 0; kt < 9; kt++) {
                int o = base + kt * 8;
                uint32_t b0 = smw[E_W1G + o], b1 = smw[E_W1G + o + 4];
                MMA_BF16(c0, a1h[kt*8+0], a1h[kt*8+1], a1h[kt*8+2], a1h[kt*8+3], b0, b1);
                MMA_BF16(c1, a1h[kt*8+4], a1h[kt*8+5], a1h[kt*8+6], a1h[kt*8+7], b0, b1);
            }
            const int n0 = nt * 8 + 2 * qid;
            const float w0 = smf[E_WG2 + n0], w1 = smf[E_WG2 + n0 + 1];
            const float b0v = smf[E_BG1 + n0], b1v = smf[E_BG1 + n0 + 1];
            ps[0] += fmaxf(c0[0] + b0v, 0.f) * w0 + fmaxf(c0[1] + b1v, 0.f) * w1;
            ps[1] += fmaxf(c0[2] + b0v, 0.f) * w0 + fmaxf(c0[3] + b1v, 0.f) * w1;
            ps[2] += fmaxf(c1[0] + b0v, 0.f) * w0 + fmaxf(c1[1] + b1v, 0.f) * w1;
            ps[3] += fmaxf(c1[2] + b0v, 0.f) * w0 + fmaxf(c1[3] + b1v, 0.f) * w1;
        }
#pragma unroll
        for (int i = 0; i < 4; i++) {
            ps[i] += __shfl_xor_sync(0xffffffffu, ps[i], 1);
            ps[i] += __shfl_xor_sync(0xffffffffu, ps[i], 2);
        }
        if (qid == 0) {
            smf[E_GATE + row0]      = 1.f / (1.f + __expf(-(ps[0] + bg2v)));
            smf[E_GATE + row0 + 8]  = 1.f / (1.f + __expf(-(ps[1] + bg2v)));
            smf[E_GATE + row0 + 16] = 1.f / (1.f + __expf(-(ps[2] + bg2v)));
            smf[E_GATE + row0 + 24] = 1.f / (1.f + __expf(-(ps[3] + bg2v)));
        }
        __syncwarp();

        uint32_t a2h[64];
        {
            const int r0w = rowbase + qid;
#pragma unroll
            for (int kt = 0; kt < 8; kt++) {
                int b0 = r0w + kt * 8;
                a2h[kt * 8 + 0] = smw[E_ACT + b0];
                a2h[kt * 8 + 1] = smw[E_ACT + b0 + 8 * ASTR];
                a2h[kt * 8 + 2] = smw[E_ACT + b0 + 4];
                a2h[kt * 8 + 3] = smw[E_ACT + b0 + 8 * ASTR + 4];
                a2h[kt * 8 + 4] = smw[E_ACT + b0 + 16 * ASTR];
                a2h[kt * 8 + 5] = smw[E_ACT + b0 + 24 * ASTR];
                a2h[kt * 8 + 6] = smw[E_ACT + b0 + 16 * ASTR + 4];
                a2h[kt * 8 + 7] = smw[E_ACT + b0 + 24 * ASTR + 4];
            }
        }
        __syncwarp();

        const float g0 = smf[E_GATE + row0];
        const float g1 = smf[E_GATE + row0 + 8];
        const float g2 = smf[E_GATE + row0 + 16];
        const float g3 = smf[E_GATE + row0 + 24];

#pragma unroll
        for (int nt = 0; nt < 8; nt++) {
            float c0[4] = {0.f, 0.f, 0.f, 0.f};
            float c1[4] = {0.f, 0.f, 0.f, 0.f};
            const int base = nt * 8 * WSTR + bq;
#pragma unroll
            for (int kt = 0; kt < 8; kt++) {
                int o = base + kt * 8;
                uint32_t b0 = smw[E_W2 + o], b1 = smw[E_W2 + o + 4];
                MMA_BF16(c0, a2h[kt*8+0], a2h[kt*8+1], a2h[kt*8+2], a2h[kt*8+3], b0, b1);
                MMA_BF16(c1, a2h[kt*8+4], a2h[kt*8+5], a2h[kt*8+6], a2h[kt*8+7], b0, b1);
            }
            const int n0 = nt * 8 + 2 * qid;
            const float b0v = smf[E_BE2 + n0], b1v = smf[E_BE2 + n0 + 1];
            *(float2*)&smf[E_ACT + rowbase + n0] =
                make_float2(g0 * (c0[0] + b0v), g0 * (c0[1] + b1v));
            *(float2*)&smf[E_ACT + rowbase + 8 * ASTR + n0] =
                make_float2(g1 * (c0[2] + b0v), g1 * (c0[3] + b1v));
            *(float2*)&smf[E_ACT + rowbase + 16 * ASTR + n0] =
                make_float2(g2 * (c1[0] + b0v), g2 * (c1[1] + b1v));
            *(float2*)&smf[E_ACT + rowbase + 24 * ASTR + n0] =
                make_float2(g3 * (c1[2] + b0v), g3 * (c1[3] + b1v));
        }
        __syncwarp();

#pragma unroll
        for (int it = 0; it < 16; it++) {
            const int j = it * 32 + l;
            const int er = j >> 4;
            const int ch = j & 15;
            const int eglobal = unit * 32 + er;
            if (eglobal < E) {
                const int tg = smi[E_TGT + w * 32 + er];
                const float4 v = *(const float4*)&smf[E_ACT + (w * 32 + er) * ASTR + ch * 4];
                red_add_v4(g_magg + (size_t)tg * 64 + ch * 4, v.x, v.y, v.z, v.w);
            }
        }
        __syncwarp();
    }
}

// ===========================================================================
// WORLD kernel: block-phase; absorbs init; weights 2-term hi/lo, activations
// 1-term bf16 (activation rounding is i.i.d. per node -> cancels in the sum).
// ===========================================================================
#define W_W1_HI 0
#define W_W1_LO 8704
#define W_W2_HI 17408
#define W_W2_LO 21760
#define W_ACT_H 26112                 // 128*76 = 9728 words
#define W_BW1   35840
#define W_RED   35968
#define W_WORDS 36480
#define W_BYTES (W_WORDS * 4)         // 145920

__global__ void __launch_bounds__(256, 1)
world_mma_kernel(const float* __restrict__ z_h, const float* __restrict__ pos_world,
                 const float* __restrict__ Ww1, const float* __restrict__ bw1,
                 const float* __restrict__ Ww2, int N) {
    extern __shared__ uint32_t smw[];
    float* smf = (float*)smw;
    uint16_t* smh = (uint16_t*)smw;

    const int t = threadIdx.x;
    const int w = t >> 5;
    const int l = t & 31;
    const int grp = l >> 2;
    const int qid = l & 3;

    // ---- init: zero g_magg + prepack z_h ----
    {
        const int nmag4 = (N * 64) >> 2;
        float4 z4 = make_float4(0.f, 0.f, 0.f, 0.f);
        for (int i = blockIdx.x * 256 + t; i < nmag4; i += gridDim.x * 256)
            ((float4*)g_magg)[i] = z4;
        const int npk = N * 32;
        for (int i = blockIdx.x * 256 + t; i < npk; i += gridDim.x * 256) {
            float2 v = ((const float2*)z_h)[i];
            g_zpk[i] = pack_hi(v.x, v.y);
        }
    }

    for (int i = t; i < 17408; i += 256) smw[W_W1_HI + i] = 0;
    __syncthreads();
    for (int idx = t; idx < 67 * 128; idx += 256) {
        int k = idx >> 7, n = idx & 127;
        float v = Ww1[idx];
        __nv_bfloat16 h = __float2bfloat16(v);
        float r = v - __bfloat162float(h);
        smh[(W_W1_HI + n * WSTR) * 2 + k] = __bfloat16_as_ushort(h);
        smh[(W_W1_LO + n * WSTR) * 2 + k] = __bfloat16_as_ushort(__float2bfloat16(r));
    }
    for (int idx = t; idx < 128 * 64; idx += 256) {
        int k = idx >> 6, n = idx & 63;
        float v = Ww2[idx];
        __nv_bfloat16 h = __float2bfloat16(v);
        float r = v - __bfloat162float(h);
        smh[(W_W2_HI + n * WSTR) * 2 + k] = __bfloat16_as_ushort(h);
        smh[(W_W2_LO + n * WSTR) * 2 + k] = __bfloat16_as_ushort(__float2bfloat16(r));
    }
    if (t < 128) smf[W_BW1 + t] = bw1[t];
    const float p0 = __ldg(&pos_world[0]);
    const float p1 = __ldg(&pos_world[1]);
    const float p2 = __ldg(&pos_world[2]);
    __syncthreads();

    const int ntiles = (N + 127) / 128;
    const int bq = grp * WSTR + qid;

    float accs[16];
#pragma unroll
    for (int i = 0; i < 16; i++) accs[i] = 0.f;

    for (int tile = blockIdx.x; tile < ntiles; tile += gridDim.x) {
        // gather: 2 threads/node, z halves, 1-term bf16
        {
            int e = t >> 1, half = t & 1;
            int n = tile * 128 + e;
            bool v = (n < N);
            const float4* zp = (const float4*)(z_h + (size_t)(v ? n : 0) * 64) + half * 8;
            uint32_t* rh = smw + W_ACT_H + e * ASTR + half * 16;
#pragma unroll
            for (int q = 0; q < 8; q++) {
                float4 x = zp[q];
                if (!v) x = make_float4(0.f, 0.f, 0.f, 0.f);
                rh[2 * q] = pack_hi(x.x, x.y);
                rh[2 * q + 1] = pack_hi(x.z, x.w);
            }
        }
        if (t < 128) {
            int n = tile * 128 + t;
            bool v = (n < N);
            float4 z0 = *(const float4*)(z_h + (size_t)(v ? n : 0) * 64);
            float d0 = v ? z0.x - p0 : 0.f;
            float d1 = v ? z0.y - p1 : 0.f;
            float d2 = v ? z0.z - p2 : 0.f;
            uint32_t* rh = smw + W_ACT_H + t * ASTR + 32;
            rh[0] = pack_hi(d0, d1);
            rh[1] = pack_hi(d2, 0.f);
#pragma unroll
            for (int q = 2; q < 8; q++) rh[q] = 0;
        }
        __syncthreads();

        uint32_t a1h[20];
        {
            const int r0w = (w * 16 + grp) * ASTR + qid;
#pragma unroll
            for (int kt = 0; kt < 5; kt++) {
                int b0 = r0w + kt * 8;
                a1h[kt * 4 + 0] = smw[W_ACT_H + b0];
                a1h[kt * 4 + 1] = smw[W_ACT_H + b0 + 8 * ASTR];
                a1h[kt * 4 + 2] = smw[W_ACT_H + b0 + 4];
                a1h[kt * 4 + 3] = smw[W_ACT_H + b0 + 8 * ASTR + 4];
            }
        }
        __syncthreads();

        const int rowbase = (w * 16 + grp) * ASTR;

        // GEMM1: Ahi*Bhi + Ahi*Blo (weights 2-term)
#pragma unroll
        for (int nt = 0; nt < 16; nt++) {
            float c[4] = {0.f, 0.f, 0.f, 0.f};
            const int base = nt * 8 * WSTR + bq;
#pragma unroll
            for (int kt = 0; kt < 5; kt++) {
                int o = base + kt * 8;
                uint32_t bh0 = smw[W_W1_HI + o], bh1 = smw[W_W1_HI + o + 4];
                uint32_t bl0 = smw[W_W1_LO + o], bl1 = smw[W_W1_LO + o + 4];
                MMA_BF16(c, a1h[kt*4], a1h[kt*4+1], a1h[kt*4+2], a1h[kt*4+3], bh0, bh1);
                MMA_BF16(c, a1h[kt*4], a1h[kt*4+1], a1h[kt*4+2], a1h[kt*4+3], bl0, bl1);
            }
            int n0 = nt * 8 + 2 * qid;
            float v0 = fmaxf(c[0] + smf[W_BW1 + n0], 0.f);
            float v1 = fmaxf(c[1] + smf[W_BW1 + n0 + 1], 0.f);
            float v2 = fmaxf(c[2] + smf[W_BW1 + n0], 0.f);
            float v3 = fmaxf(c[3] + smf[W_BW1 + n0 + 1], 0.f);
            int wi = rowbase + nt * 4 + qid;
            smw[W_ACT_H + wi] = pack_hi(v0, v1);
            smw[W_ACT_H + wi + 8 * ASTR] = pack_hi(v2, v3);
        }
        __syncthreads();

        uint32_t a2h[32];
        {
            const int r0w = rowbase + qid;
#pragma unroll
            for (int kt = 0; kt < 8; kt++) {
                int b0 = r0w + kt * 8;
                a2h[kt * 4 + 0] = smw[W_ACT_H + b0];
                a2h[kt * 4 + 1] = smw[W_ACT_H + b0 + 8 * ASTR];
                a2h[kt * 4 + 2] = smw[W_ACT_H + b0 + 4];
                a2h[kt * 4 + 3] = smw[W_ACT_H + b0 + 8 * ASTR + 4];
            }
        }
        const int r0 = tile * 128 + w * 16 + grp;
        const float m0 = (r0 < N) ? 1.f : 0.f;
        const float m1 = (r0 + 8 < N) ? 1.f : 0.f;

        // GEMM2: Ahi*Bhi + Ahi*Blo, masked accumulate
#pragma unroll
        for (int nt = 0; nt < 8; nt++) {
            float c[4] = {0.f, 0.f, 0.f, 0.f};
            const int base = nt * 8 * WSTR + bq;
#pragma unroll
            for (int kt = 0; kt < 8; kt++) {
                int o = base + kt * 8;
                uint32_t bh0 = smw[W_W2_HI + o], bh1 = smw[W_W2_HI + o + 4];
                uint32_t bl0 = smw[W_W2_LO + o], bl1 = smw[W_W2_LO + o + 4];
                MMA_BF16(c, a2h[kt*4], a2h[kt*4+1], a2h[kt*4+2], a2h[kt*4+3], bh0, bh1);
                MMA_BF16(c, a2h[kt*4], a2h[kt*4+1], a2h[kt*4+2], a2h[kt*4+3], bl0, bl1);
            }
            accs[nt * 2]     += m0 * c[0] + m1 * c[2];
            accs[nt * 2 + 1] += m0 * c[1] + m1 * c[3];
        }
        __syncthreads();
    }

#pragma unroll
    for (int i = 0; i < 16; i++) {
        accs[i] += __shfl_xor_sync(0xffffffffu, accs[i], 4);
        accs[i] += __shfl_xor_sync(0xffffffffu, accs[i], 8);
        accs[i] += __shfl_xor_sync(0xffffffffu, accs[i], 16);
    }
    if (l < 4) {
#pragma unroll
        for (int nt = 0; nt < 8; nt++) {
            smf[W_RED + w * 64 + nt * 8 + 2 * l]     = accs[nt * 2];
            smf[W_RED + w * 64 + nt * 8 + 2 * l + 1] = accs[nt * 2 + 1];
        }
    }
    __syncthreads();
    if (t < 64) {
        float s = 0.f;
#pragma unroll
        for (int ww = 0; ww < 8; ww++) s += smf[W_RED + ww * 64 + t];
        g_wpart[blockIdx.x * 64 + t] = s;
    }
}

// ===========================================================================
// NODE kernel: unchanged (GEMM1 1-term + exact fp32 hid offset, GEMM2 3-term)
// ===========================================================================
#define N_W1    0
#define N_W2_HI 8704
#define N_W2_LO 13056
#define N_ACT_H 17408
#define N_ACT_L 27136
#define N_HOFF  36864
#define N_WS    36992
#define N_WORDS 37056
#define N_BYTES (N_WORDS * 4)

__global__ void __launch_bounds__(256, 1)
node_mma_kernel(const float* __restrict__ z_h,
                const float* __restrict__ Wn1, const float* __restrict__ bn1,
                const float* __restrict__ Wn2, const float* __restrict__ bn2,
                const float* __restrict__ bw2,
                float* __restrict__ out, int N, int nwblocks) {
    extern __shared__ uint32_t smw[];
    float* smf = (float*)smw;
    uint16_t* smh = (uint16_t*)smw;

    const int t = threadIdx.x;
    const int w = t >> 5;
    const int l = t & 31;
    const int grp = l >> 2;
    const int qid = l & 3;

    for (int idx = t; idx < 128 * 128; idx += 256) {
        int k = idx >> 7, n = idx & 127;
        smh[(N_W1 + n * WSTR) * 2 + k] = __bfloat16_as_ushort(__float2bfloat16(Wn1[idx]));
    }
    for (int idx = t; idx < 128 * 64; idx += 256) {
        int k = idx >> 6, n = idx & 63;
        float v = Wn2[idx];
        __nv_bfloat16 h = __float2bfloat16(v);
        float r = v - __bfloat162float(h);
        smh[(N_W2_HI + n * WSTR) * 2 + k] = __bfloat16_as_ushort(h);
        smh[(N_W2_LO + n * WSTR) * 2 + k] = __bfloat16_as_ushort(__float2bfloat16(r));
    }
    if (t < 64) {
        float s = (float)N * __ldg(&bw2[t]);
        for (int b = 0; b < nwblocks; b++) s += g_wpart[b * 64 + t];
        smf[N_WS + t] = s;
    }
    __syncthreads();
    if (t < 128) {
        float acc = __ldg(&bn1[t]);
#pragma unroll 4
        for (int k = 0; k < 64; k++)
            acc = fmaf(smf[N_WS + k], __ldg(&Wn1[(64 + k) * 128 + t]), acc);
        smf[N_HOFF + t] = acc;
    }
    __syncthreads();

    const int ntiles = (N + 127) / 128;
    const int bq = grp * WSTR + qid;

    for (int tile = blockIdx.x; tile < ntiles; tile += gridDim.x) {
        {
            int e = t >> 1, half = t & 1;
            int n = tile * 128 + e;
            bool v = (n < N);
            const float4* srcp = half
                ? (const float4*)(g_magg + (size_t)(v ? n : 0) * 64)
                : (const float4*)(z_h + (size_t)(v ? n : 0) * 64);
            uint32_t* rh = smw + N_ACT_H + e * ASTR + half * 32;
#pragma unroll
            for (int q = 0; q < 16; q++) {
                float4 x = srcp[q];
                if (!v) x = make_float4(0.f, 0.f, 0.f, 0.f);
                rh[2 * q] = pack_hi(x.x, x.y);
                rh[2 * q + 1] = pack_hi(x.z, x.w);
            }
        }
        __syncthreads();

        uint32_t a1h[32];
        {
            const int r0w = (w * 16 + grp) * ASTR + qid;
#pragma unroll
            for (int kt = 0; kt < 8; kt++) {
                int b0 = r0w + kt * 8;
                a1h[kt * 4 + 0] = smw[N_ACT_H + b0];
                a1h[kt * 4 + 1] = smw[N_ACT_H + b0 + 8 * ASTR];
                a1h[kt * 4 + 2] = smw[N_ACT_H + b0 + 4];
                a1h[kt * 4 + 3] = smw[N_ACT_H + b0 + 8 * ASTR + 4];
            }
        }
        __syncthreads();

        const int rowbase = (w * 16 + grp) * ASTR;

#pragma unroll
        for (int nt2 = 0; nt2 < 8; nt2++) {
            const int ntA = nt2 * 2, ntB = ntA + 1;
            float cA[4] = {0.f, 0.f, 0.f, 0.f};
            float cB[4] = {0.f, 0.f, 0.f, 0.f};
            const int baseA = ntA * 8 * WSTR + bq;
            const int baseB = ntB * 8 * WSTR + bq;
#pragma unroll
            for (int kt = 0; kt < 8; kt++) {
                int oA = baseA + kt * 8, oB = baseB + kt * 8;
                uint32_t bA0 = smw[N_W1 + oA], bA1 = smw[N_W1 + oA + 4];
                uint32_t bB0 = smw[N_W1 + oB], bB1 = smw[N_W1 + oB + 4];
                MMA_BF16(cA, a1h[kt*4], a1h[kt*4+1], a1h[kt*4+2], a1h[kt*4+3], bA0, bA1);
                MMA_BF16(cB, a1h[kt*4], a1h[kt*4+1], a1h[kt*4+2], a1h[kt*4+3], bB0, bB1);
            }
#pragma unroll
            for (int s = 0; s < 2; s++) {
                const float* c = s ? cB : cA;
                const int nt = s ? ntB : ntA;
                const int n0 = nt * 8 + 2 * qid;
                const float h0v = smf[N_HOFF + n0], h1v = smf[N_HOFF + n0 + 1];
                float v0 = fmaxf(c[0] + h0v, 0.f);
                float v1 = fmaxf(c[1] + h1v, 0.f);
                float v2 = fmaxf(c[2] + h0v, 0.f);
                float v3 = fmaxf(c[3] + h1v, 0.f);
                uint32_t hh0, ll0, hh1, ll1;
                pack_pair(v0, v1, hh0, ll0);
                pack_pair(v2, v3, hh1, ll1);
                int wi = rowbase + nt * 4 + qid;
                smw[N_ACT_H + wi] = hh0;
                smw[N_ACT_L + wi] = ll0;
                smw[N_ACT_H + wi + 8 * ASTR] = hh1;
                smw[N_ACT_L + wi + 8 * ASTR] = ll1;
            }
        }
        __syncwarp();

        uint32_t a2h[32], a2l[32];
        {
            const int r0w = rowbase + qid;
#pragma unroll
            for (int kt = 0; kt < 8; kt++) {
                int b0 = r0w + kt * 8;
                a2h[kt * 4 + 0] = smw[N_ACT_H + b0];
                a2h[kt * 4 + 1] = smw[N_ACT_H + b0 + 8 * ASTR];
                a2h[kt * 4 + 2] = smw[N_ACT_H + b0 + 4];
                a2h[kt * 4 + 3] = smw[N_ACT_H + b0 + 8 * ASTR + 4];
                a2l[kt * 4 + 0] = smw[N_ACT_L + b0];
                a2l[kt * 4 + 1] = smw[N_ACT_L + b0 + 8 * ASTR];
                a2l[kt * 4 + 2] = smw[N_ACT_L + b0 + 4];
                a2l[kt * 4 + 3] = smw[N_ACT_L + b0 + 8 * ASTR + 4];
            }
        }
        const int r0 = tile * 128 + w * 16 + grp;
        const int r1 = r0 + 8;

#pragma unroll
        for (int nt = 0; nt < 8; nt++) {
            float c[4] = {0.f, 0.f, 0.f, 0.f};
            const int base = nt * 8 * WSTR + bq;
#pragma unroll
            for (int kt = 0; kt < 8; kt++) {
                int o = base + kt * 8;
                uint32_t bh0 = smw[N_W2_HI + o], bh1 = smw[N_W2_HI + o + 4];
                uint32_t bl0 = smw[N_W2_LO + o], bl1 = smw[N_W2_LO + o + 4];
                MMA_BF16(c, a2h[kt*4], a2h[kt*4+1], a2h[kt*4+2], a2h[kt*4+3], bh0, bh1);
                MMA_BF16(c, a2l[kt*4], a2l[kt*4+1], a2l[kt*4+2], a2l[kt*4+3], bh0, bh1);
                MMA_BF16(c, a2h[kt*4], a2h[kt*4+1], a2h[kt*4+2], a2h[kt*4+3], bl0, bl1);
            }
            int n0 = nt * 8 + 2 * qid;
            float b0v = __ldg(&bn2[n0]), b1v = __ldg(&bn2[n0 + 1]);
            if (r0 < N) {
                float2 o2 = make_float2(c[0] + b0v, c[1] + b1v);
                *(float2*)(out + (size_t)r0 * 64 + n0) = o2;
            }
            if (r1 < N) {
                float2 o2 = make_float2(c[2] + b0v, c[3] + b1v);
                *(float2*)(out + (size_t)r1 * 64 + n0) = o2;
            }
        }
        __syncthreads();
    }
}

// ===========================================================================
extern "C" void kernel_launch(void* const* d_in, const int* in_sizes, int n_in,
                              void* d_out, int out_size) {
    const float* z_h       = (const float*)d_in[0];
    const float* pos_world = (const float*)d_in[1];
    const int*   ei        = (const int*)d_in[2];
    const float* We1 = (const float*)d_in[3];
    const float* be1 = (const float*)d_in[4];
    const float* We2 = (const float*)d_in[5];
    const float* be2 = (const float*)d_in[6];
    const float* Wg1 = (const float*)d_in[7];
    const float* bg1 = (const float*)d_in[8];
    const float* Wg2 = (const float*)d_in[9];
    const float* bg2 = (const float*)d_in[10];
    const float* Wn1 = (const float*)d_in[11];
    const float* bn1 = (const float*)d_in[12];
    const float* Wn2 = (const float*)d_in[13];
    const float* bn2 = (const float*)d_in[14];
    const float* Ww1 = (const float*)d_in[15];
    const float* bw1 = (const float*)d_in[16];
    const float* Ww2 = (const float*)d_in[17];
    const float* bw2 = (const float*)d_in[18];

    const int N = in_sizes[0] / 64;
    const int E = in_sizes[2] / 2;
    float* out = (float*)d_out;

    cudaFuncSetAttribute(edge_mma_kernel,
                         cudaFuncAttributeMaxDynamicSharedMemorySize, E_BYTES);
    cudaFuncSetAttribute(node_mma_kernel,
                         cudaFuncAttributeMaxDynamicSharedMemorySize, N_BYTES);
    cudaFuncSetAttribute(world_mma_kernel,
                         cudaFuncAttributeMaxDynamicSharedMemorySize, W_BYTES);

    const int NWB = 148;
    world_mma_kernel<<<NWB, 256, W_BYTES>>>(z_h, pos_world, Ww1, bw1, Ww2, N);
    edge_mma_kernel<<<148, ETHREADS, E_BYTES>>>(ei, We1, be1, We2, be2,
                                                Wg1, bg1, Wg2, bg2, E);
    node_mma_kernel<<<148, 256, N_BYTES>>>(z_h, Wn1, bn1, Wn2, bn2, bw2,
                                           out, N, NWB);
}

// round 16
// speedup vs baseline: 1.0113x; 1.0113x over previous
#include <cuda_runtime.h>
#include <cuda_bf16.h>
#include <math.h>
#include <stdint.h>

// ===========================================================================
// Scratch (no allocations allowed)
// ===========================================================================
__device__ float g_magg[50048 * 64];
__device__ float g_wpart[148 * 64];
__device__ uint32_t g_zpk[50048 * 32];   // prepacked bf16x2 z_h

// ===========================================================================
// warp MMA m16n8k16 bf16 (sm_80+ PTX, no arch suffix)
// ===========================================================================
#define MMA_BF16(c, a0, a1, a2, a3, b0, b1) \
    asm volatile("mma.sync.aligned.m16n8k16.row.col.f32.bf16.bf16.f32 " \
        "{%0,%1,%2,%3},{%4,%5,%6,%7},{%8,%9},{%0,%1,%2,%3};" \
        : "+f"((c)[0]), "+f"((c)[1]), "+f"((c)[2]), "+f"((c)[3]) \
        : "r"(a0), "r"(a1), "r"(a2), "r"(a3), "r"(b0), "r"(b1))

__device__ __forceinline__ void red_add_v4(float* addr, float x, float y, float z, float w_) {
    asm volatile("red.global.add.v4.f32 [%0], {%1, %2, %3, %4};"
                 :: "l"(addr), "f"(x), "f"(y), "f"(z), "f"(w_) : "memory");
}

__device__ __forceinline__ uint32_t pack_hi(float v0, float v1) {
    return ((uint32_t)__bfloat16_as_ushort(__float2bfloat16(v1)) << 16) |
           (uint32_t)__bfloat16_as_ushort(__float2bfloat16(v0));
}

__device__ __forceinline__ void pack_pair(float v0, float v1, uint32_t& hi, uint32_t& lo) {
    __nv_bfloat16 h0 = __float2bfloat16(v0);
    __nv_bfloat16 h1 = __float2bfloat16(v1);
    float r0 = v0 - __bfloat162float(h0);
    float r1 = v1 - __bfloat162float(h1);
    hi = ((uint32_t)__bfloat16_as_ushort(h1) << 16) | (uint32_t)__bfloat16_as_ushort(h0);
    lo = ((uint32_t)__bfloat16_as_ushort(__float2bfloat16(r1)) << 16) |
         (uint32_t)__bfloat16_as_ushort(__float2bfloat16(r0));
}

__device__ __forceinline__ float bf_lo(uint32_t u) {
    return __bfloat162float(__ushort_as_bfloat16((unsigned short)(u & 0xffffu)));
}
__device__ __forceinline__ float bf_hi(uint32_t u) {
    return __bfloat162float(__ushort_as_bfloat16((unsigned short)(u >> 16)));
}

#define ASTR 76   // activation row stride, words (mod32=12, conflict-free)
#define WSTR 68   // weight row stride, words (mod32=4, conflict-free)

// ===========================================================================
// EDGE kernel: 12 warps x 32-edge units, 1-term bf16 weights,
// separate msg/gate passes, red.v4 scatter (measured best ~276us).
// ===========================================================================
#define ETHREADS 384
#define EWARPS   12

#define E_W1E   0
#define E_W1G   8704
#define E_W2    17408
#define E_ACT   21760
#define E_TGT   50944
#define E_GATE  51328
#define E_BE1   51712
#define E_BG1   51840
#define E_WG2   51968
#define E_BE2   52096
#define E_WORDS 52160
#define E_BYTES (E_WORDS * 4)

__global__ void __launch_bounds__(ETHREADS, 1)
edge_mma_kernel(const int* __restrict__ ei,
                const float* __restrict__ We1, const float* __restrict__ be1,
                const float* __restrict__ We2, const float* __restrict__ be2,
                const float* __restrict__ Wg1, const float* __restrict__ bg1,
                const float* __restrict__ Wg2, const float* __restrict__ bg2,
                int E) {
    extern __shared__ uint32_t smw[];
    float* smf = (float*)smw;
    int* smi = (int*)smw;
    uint16_t* smh = (uint16_t*)smw;

    const int t = threadIdx.x;
    const int w = t >> 5;
    const int l = t & 31;
    const int grp = l >> 2;
    const int qid = l & 3;

    for (int idx = t; idx < 136 * 128; idx += ETHREADS) {
        int k = idx >> 7, n = idx & 127;
        smh[(E_W1E + n * WSTR) * 2 + k] = __bfloat16_as_ushort(__float2bfloat16(We1[idx]));
        smh[(E_W1G + n * WSTR) * 2 + k] = __bfloat16_as_ushort(__float2bfloat16(Wg1[idx]));
    }
    for (int idx = t; idx < 128 * 64; idx += ETHREADS) {
        int k = idx >> 6, n = idx & 63;
        smh[(E_W2 + n * WSTR) * 2 + k] = __bfloat16_as_ushort(__float2bfloat16(We2[idx]));
    }
    if (t < 128) {
        smf[E_BE1 + t] = be1[t];
        smf[E_BG1 + t] = bg1[t];
        smf[E_WG2 + t] = Wg2[t];
    }
    if (t < 64) smf[E_BE2 + t] = be2[t];
    const float bg2v = __ldg(&bg2[0]);
    __syncthreads();

    const int nunits = (E + 31) / 32;
    const int bq = grp * WSTR + qid;
    const int e_local = w * 32 + l;
    uint32_t* const myrow = smw + E_ACT + e_local * ASTR;
    const int rowbase = (w * 32 + grp) * ASTR;
    const int row0 = w * 32 + grp;

    for (int unit = blockIdx.x * EWARPS + w; unit < nunits; unit += gridDim.x * EWARPS) {
        const int eg = unit * 32 + l;
        const int sN = (eg < E) ? ei[eg] : 0;
        const int tN = (eg < E) ? ei[E + eg] : 0;
        smi[E_TGT + e_local] = tN;
        const uint4* zs = (const uint4*)(g_zpk + (size_t)sN * 32);
        const uint4* zt = (const uint4*)(g_zpk + (size_t)tN * 32);
        uint4 s0 = zs[0];
        uint4 t0 = zt[0];
        myrow[0] = s0.x; myrow[1] = s0.y; myrow[2] = s0.z; myrow[3] = s0.w;
        myrow[32] = t0.x; myrow[33] = t0.y; myrow[34] = t0.z; myrow[35] = t0.w;
#pragma unroll
        for (int q = 1; q < 8; q++) {
            uint4 v = zs[q];
            myrow[4 * q] = v.x; myrow[4 * q + 1] = v.y;
            myrow[4 * q + 2] = v.z; myrow[4 * q + 3] = v.w;
        }
#pragma unroll
        for (int q = 1; q < 8; q++) {
            uint4 v = zt[q];
            myrow[32 + 4 * q] = v.x; myrow[33 + 4 * q] = v.y;
            myrow[34 + 4 * q] = v.z; myrow[35 + 4 * q] = v.w;
        }
        {
            float a0 = bf_lo(s0.x), a1 = bf_hi(s0.x), a2 = bf_lo(s0.y);
            float a3 = bf_hi(s0.y), a4 = bf_lo(s0.z), a5 = bf_hi(s0.z);
            float b0 = bf_lo(t0.x), b1 = bf_hi(t0.x), b2 = bf_lo(t0.y);
            float b3 = bf_hi(t0.y), b4 = bf_lo(t0.z), b5 = bf_hi(t0.z);
            float dx = a0 - b0, dy = a1 - b1, dz = a2 - b2;
            float dist = dx * dx + dy * dy + dz * dz;
            float cx = a4 * b5 - a5 * b4;
            float cy = a5 * b3 - a3 * b5;
            float cz = a3 * b4 - a4 * b3;
            float cn = sqrtf(cx * cx + cy * cy + cz * cz);
            myrow[64] = pack_hi(dx, dy);
            myrow[65] = pack_hi(dz, dist);
            myrow[66] = pack_hi(cx, cy);
            myrow[67] = pack_hi(cz, cn);
            myrow[68] = 0; myrow[69] = 0; myrow[70] = 0; myrow[71] = 0;
        }
        __syncwarp();

        uint32_t a1h[72];
        {
            const int r0w = rowbase + qid;
#pragma unroll
            for (int kt = 0; kt < 9; kt++) {
                int b0 = r0w + kt * 8;
                a1h[kt * 8 + 0] = smw[E_ACT + b0];
                a1h[kt * 8 + 1] = smw[E_ACT + b0 + 8 * ASTR];
                a1h[kt * 8 + 2] = smw[E_ACT + b0 + 4];
                a1h[kt * 8 + 3] = smw[E_ACT + b0 + 8 * ASTR + 4];
                a1h[kt * 8 + 4] = smw[E_ACT + b0 + 16 * ASTR];
                a1h[kt * 8 + 5] = smw[E_ACT + b0 + 24 * ASTR];
                a1h[kt * 8 + 6] = smw[E_ACT + b0 + 16 * ASTR + 4];
                a1h[kt * 8 + 7] = smw[E_ACT + b0 + 24 * ASTR + 4];
            }
        }
        __syncwarp();

#pragma unroll
        for (int nt = 0; nt < 16; nt++) {
            float c0[4] = {0.f, 0.f, 0.f, 0.f};
            float c1[4] = {0.f, 0.f, 0.f, 0.f};
            const int base = nt * 8 * WSTR + bq;
#pragma unroll
            for (int kt = 0; kt < 9; kt++) {
                int o = base + kt * 8;
                uint32_t b0 = smw[E_W1E + o], b1 = smw[E_W1E + o + 4];
                MMA_BF16(c0, a1h[kt*8+0], a1h[kt*8+1], a1h[kt*8+2], a1h[kt*8+3], b0, b1);
                MMA_BF16(c1, a1h[kt*8+4], a1h[kt*8+5], a1h[kt*8+6], a1h[kt*8+7], b0, b1);
            }
            const int n0 = nt * 8 + 2 * qid;
            const float be0 = smf[E_BE1 + n0], be1v = smf[E_BE1 + n0 + 1];
            const int wi = rowbase + nt * 4 + qid;
            smw[E_ACT + wi] =
                pack_hi(fmaxf(c0[0] + be0, 0.f), fmaxf(c0[1] + be1v, 0.f));
            smw[E_ACT + wi + 8 * ASTR] =
                pack_hi(fmaxf(c0[2] + be0, 0.f), fmaxf(c0[3] + be1v, 0.f));
            smw[E_ACT + wi + 16 * ASTR] =
                pack_hi(fmaxf(c1[0] + be0, 0.f), fmaxf(c1[1] + be1v, 0.f));
            smw[E_ACT + wi + 24 * ASTR] =
                pack_hi(fmaxf(c1[2] + be0, 0.f), fmaxf(c1[3] + be1v, 0.f));
        }

        float ps[4] = {0.f, 0.f, 0.f, 0.f};
#pragma unroll
        for (int nt = 0; nt < 16; nt++) {
            float c0[4] = {0.f, 0.f, 0.f, 0.f};
            float c1[4] = {0.f, 0.f, 0.f, 0.f};
            const int base = nt * 8 * WSTR + bq;
#pragma unroll
            for (int kt = 0; kt < 9; kt++) {
                int o = base + kt * 8;
                uint32_t b0 = smw[E_W1G + o], b1 = smw[E_W1G + o + 4];
                MMA_BF16(c0, a1h[kt*8+0], a1h[kt*8+1], a1h[kt*8+2], a1h[kt*8+3], b0, b1);
                MMA_BF16(c1, a1h[kt*8+4], a1h[kt*8+5], a1h[kt*8+6], a1h[kt*8+7], b0, b1);
            }
            const int n0 = nt * 8 + 2 * qid;
            const float w0 = smf[E_WG2 + n0], w1 = smf[E_WG2 + n0 + 1];
            const float b0v = smf[E_BG1 + n0], b1v = smf[E_BG1 + n0 + 1];
            ps[0] += fmaxf(c0[0] + b0v, 0.f) * w0 + fmaxf(c0[1] + b1v, 0.f) * w1;
            ps[1] += fmaxf(c0[2] + b0v, 0.f) * w0 + fmaxf(c0[3] + b1v, 0.f) * w1;
            ps[2] += fmaxf(c1[0] + b0v, 0.f) * w0 + fmaxf(c1[1] + b1v, 0.f) * w1;
            ps[3] += fmaxf(c1[2] + b0v, 0.f) * w0 + fmaxf(c1[3] + b1v, 0.f) * w1;
        }
#pragma unroll
        for (int i = 0; i < 4; i++) {
            ps[i] += __shfl_xor_sync(0xffffffffu, ps[i], 1);
            ps[i] += __shfl_xor_sync(0xffffffffu, ps[i], 2);
        }
        if (qid == 0) {
            smf[E_GATE + row0]      = 1.f / (1.f + __expf(-(ps[0] + bg2v)));
            smf[E_GATE + row0 + 8]  = 1.f / (1.f + __expf(-(ps[1] + bg2v)));
            smf[E_GATE + row0 + 16] = 1.f / (1.f + __expf(-(ps[2] + bg2v)));
            smf[E_GATE + row0 + 24] = 1.f / (1.f + __expf(-(ps[3] + bg2v)));
        }
        __syncwarp();

        uint32_t a2h[64];
        {
            const int r0w = rowbase + qid;
#pragma unroll
            for (int kt = 0; kt < 8; kt++) {
                int b0 = r0w + kt * 8;
                a2h[kt * 8 + 0] = smw[E_ACT + b0];
                a2h[kt * 8 + 1] = smw[E_ACT + b0 + 8 * ASTR];
                a2h[kt * 8 + 2] = smw[E_ACT + b0 + 4];
                a2h[kt * 8 + 3] = smw[E_ACT + b0 + 8 * ASTR + 4];
                a2h[kt * 8 + 4] = smw[E_ACT + b0 + 16 * ASTR];
                a2h[kt * 8 + 5] = smw[E_ACT + b0 + 24 * ASTR];
                a2h[kt * 8 + 6] = smw[E_ACT + b0 + 16 * ASTR + 4];
                a2h[kt * 8 + 7] = smw[E_ACT + b0 + 24 * ASTR + 4];
            }
        }
        __syncwarp();

        const float g0 = smf[E_GATE + row0];
        const float g1 = smf[E_GATE + row0 + 8];
        const float g2 = smf[E_GATE + row0 + 16];
        const float g3 = smf[E_GATE + row0 + 24];

#pragma unroll
        for (int nt = 0; nt < 8; nt++) {
            float c0[4] = {0.f, 0.f, 0.f, 0.f};
            float c1[4] = {0.f, 0.f, 0.f, 0.f};
            const int base = nt * 8 * WSTR + bq;
#pragma unroll
            for (int kt = 0; kt < 8; kt++) {
                int o = base + kt * 8;
                uint32_t b0 = smw[E_W2 + o], b1 = smw[E_W2 + o + 4];
                MMA_BF16(c0, a2h[kt*8+0], a2h[kt*8+1], a2h[kt*8+2], a2h[kt*8+3], b0, b1);
                MMA_BF16(c1, a2h[kt*8+4], a2h[kt*8+5], a2h[kt*8+6], a2h[kt*8+7], b0, b1);
            }
            const int n0 = nt * 8 + 2 * qid;
            const float b0v = smf[E_BE2 + n0], b1v = smf[E_BE2 + n0 + 1];
            *(float2*)&smf[E_ACT + rowbase + n0] =
                make_float2(g0 * (c0[0] + b0v), g0 * (c0[1] + b1v));
            *(float2*)&smf[E_ACT + rowbase + 8 * ASTR + n0] =
                make_float2(g1 * (c0[2] + b0v), g1 * (c0[3] + b1v));
            *(float2*)&smf[E_ACT + rowbase + 16 * ASTR + n0] =
                make_float2(g2 * (c1[0] + b0v), g2 * (c1[1] + b1v));
            *(float2*)&smf[E_ACT + rowbase + 24 * ASTR + n0] =
                make_float2(g3 * (c1[2] + b0v), g3 * (c1[3] + b1v));
        }
        __syncwarp();

#pragma unroll
        for (int it = 0; it < 16; it++) {
            const int j = it * 32 + l;
            const int er = j >> 4;
            const int ch = j & 15;
            const int eglobal = unit * 32 + er;
            if (eglobal < E) {
                const int tg = smi[E_TGT + w * 32 + er];
                const float4 v = *(const float4*)&smf[E_ACT + (w * 32 + er) * ASTR + ch * 4];
                red_add_v4(g_magg + (size_t)tg * 64 + ch * 4, v.x, v.y, v.z, v.w);
            }
        }
        __syncwarp();
    }
}

// ===========================================================================
// WORLD kernel: block-phase; absorbs init; 3-term bf16 MMA;
// per-block partials to g_wpart.
// ===========================================================================
#define W_W1_HI 0
#define W_W1_LO 8704
#define W_W2_HI 17408
#define W_W2_LO 21760
#define W_ACT_H 26112
#define W_ACT_L 35840
#define W_BW1   45568
#define W_RED   45696
#define W_WORDS 46208
#define W_BYTES (W_WORDS * 4)

__global__ void __launch_bounds__(256, 1)
world_mma_kernel(const float* __restrict__ z_h, const float* __restrict__ pos_world,
                 const float* __restrict__ Ww1, const float* __restrict__ bw1,
                 const float* __restrict__ Ww2, int N) {
    extern __shared__ uint32_t smw[];
    float* smf = (float*)smw;
    uint16_t* smh = (uint16_t*)smw;

    const int t = threadIdx.x;
    const int w = t >> 5;
    const int l = t & 31;
    const int grp = l >> 2;
    const int qid = l & 3;

    // ---- init: zero g_magg + prepack z_h ----
    {
        const int nmag4 = (N * 64) >> 2;
        float4 z4 = make_float4(0.f, 0.f, 0.f, 0.f);
        for (int i = blockIdx.x * 256 + t; i < nmag4; i += gridDim.x * 256)
            ((float4*)g_magg)[i] = z4;
        const int npk = N * 32;
        for (int i = blockIdx.x * 256 + t; i < npk; i += gridDim.x * 256) {
            float2 v = ((const float2*)z_h)[i];
            g_zpk[i] = pack_hi(v.x, v.y);
        }
    }

    for (int i = t; i < 17408; i += 256) smw[W_W1_HI + i] = 0;
    __syncthreads();
    for (int idx = t; idx < 67 * 128; idx += 256) {
        int k = idx >> 7, n = idx & 127;
        float v = Ww1[idx];
        __nv_bfloat16 h = __float2bfloat16(v);
        float r = v - __bfloat162float(h);
        smh[(W_W1_HI + n * WSTR) * 2 + k] = __bfloat16_as_ushort(h);
        smh[(W_W1_LO + n * WSTR) * 2 + k] = __bfloat16_as_ushort(__float2bfloat16(r));
    }
    for (int idx = t; idx < 128 * 64; idx += 256) {
        int k = idx >> 6, n = idx & 63;
        float v = Ww2[idx];
        __nv_bfloat16 h = __float2bfloat16(v);
        float r = v - __bfloat162float(h);
        smh[(W_W2_HI + n * WSTR) * 2 + k] = __bfloat16_as_ushort(h);
        smh[(W_W2_LO + n * WSTR) * 2 + k] = __bfloat16_as_ushort(__float2bfloat16(r));
    }
    if (t < 128) smf[W_BW1 + t] = bw1[t];
    const float p0 = __ldg(&pos_world[0]);
    const float p1 = __ldg(&pos_world[1]);
    const float p2 = __ldg(&pos_world[2]);
    __syncthreads();

    const int ntiles = (N + 127) / 128;
    const int bq = grp * WSTR + qid;

    float accs[16];
#pragma unroll
    for (int i = 0; i < 16; i++) accs[i] = 0.f;

    for (int tile = blockIdx.x; tile < ntiles; tile += gridDim.x) {
        {
            int e = t >> 1, half = t & 1;
            int n = tile * 128 + e;
            bool v = (n < N);
            const float4* zp = (const float4*)(z_h + (size_t)(v ? n : 0) * 64) + half * 8;
            uint32_t* rh = smw + W_ACT_H + e * ASTR + half * 16;
            uint32_t* rl = smw + W_ACT_L + e * ASTR + half * 16;
#pragma unroll
            for (int q = 0; q < 8; q++) {
                float4 x = zp[q];
                if (!v) x = make_float4(0.f, 0.f, 0.f, 0.f);
                uint32_t h0, l0, h1, l1;
                pack_pair(x.x, x.y, h0, l0);
                pack_pair(x.z, x.w, h1, l1);
                rh[2 * q] = h0; rh[2 * q + 1] = h1;
                rl[2 * q] = l0; rl[2 * q + 1] = l1;
            }
        }
        if (t < 128) {
            int n = tile * 128 + t;
            bool v = (n < N);
            float4 z0 = *(const float4*)(z_h + (size_t)(v ? n : 0) * 64);
            float d0 = v ? z0.x - p0 : 0.f;
            float d1 = v ? z0.y - p1 : 0.f;
            float d2 = v ? z0.z - p2 : 0.f;
            uint32_t* rh = smw + W_ACT_H + t * ASTR + 32;
            uint32_t* rl = smw + W_ACT_L + t * ASTR + 32;
            uint32_t h0, l0, h1, l1;
            pack_pair(d0, d1, h0, l0);
            pack_pair(d2, 0.f, h1, l1);
            rh[0] = h0; rl[0] = l0;
            rh[1] = h1; rl[1] = l1;
#pragma unroll
            for (int q = 2; q < 8; q++) { rh[q] = 0; rl[q] = 0; }
        }
        __syncthreads();

        uint32_t a1h[20], a1l[20];
        {
            const int r0w = (w * 16 + grp) * ASTR + qid;
#pragma unroll
            for (int kt = 0; kt < 5; kt++) {
                int b0 = r0w + kt * 8;
                a1h[kt * 4 + 0] = smw[W_ACT_H + b0];
                a1h[kt * 4 + 1] = smw[W_ACT_H + b0 + 8 * ASTR];
                a1h[kt * 4 + 2] = smw[W_ACT_H + b0 + 4];
                a1h[kt * 4 + 3] = smw[W_ACT_H + b0 + 8 * ASTR + 4];
                a1l[kt * 4 + 0] = smw[W_ACT_L + b0];
                a1l[kt * 4 + 1] = smw[W_ACT_L + b0 + 8 * ASTR];
                a1l[kt * 4 + 2] = smw[W_ACT_L + b0 + 4];
                a1l[kt * 4 + 3] = smw[W_ACT_L + b0 + 8 * ASTR + 4];
            }
        }
        __syncthreads();

        const int rowbase = (w * 16 + grp) * ASTR;

#pragma unroll
        for (int nt = 0; nt < 16; nt++) {
            float c[4] = {0.f, 0.f, 0.f, 0.f};
            const int base = nt * 8 * WSTR + bq;
#pragma unroll
            for (int kt = 0; kt < 5; kt++) {
                int o = base + kt * 8;
                uint32_t bh0 = smw[W_W1_HI + o], bh1 = smw[W_W1_HI + o + 4];
                uint32_t bl0 = smw[W_W1_LO + o], bl1 = smw[W_W1_LO + o + 4];
                MMA_BF16(c, a1h[kt*4], a1h[kt*4+1], a1h[kt*4+2], a1h[kt*4+3], bh0, bh1);
                MMA_BF16(c, a1l[kt*4], a1l[kt*4+1], a1l[kt*4+2], a1l[kt*4+3], bh0, bh1);
                MMA_BF16(c, a1h[kt*4], a1h[kt*4+1], a1h[kt*4+2], a1h[kt*4+3], bl0, bl1);
            }
            int n0 = nt * 8 + 2 * qid;
            float v0 = fmaxf(c[0] + smf[W_BW1 + n0], 0.f);
            float v1 = fmaxf(c[1] + smf[W_BW1 + n0 + 1], 0.f);
            float v2 = fmaxf(c[2] + smf[W_BW1 + n0], 0.f);
            float v3 = fmaxf(c[3] + smf[W_BW1 + n0 + 1], 0.f);
            uint32_t h0, l0, h1, l1;
            pack_pair(v0, v1, h0, l0);
            pack_pair(v2, v3, h1, l1);
            int wi = rowbase + nt * 4 + qid;
            smw[W_ACT_H + wi] = h0;
            smw[W_ACT_L + wi] = l0;
            smw[W_ACT_H + wi + 8 * ASTR] = h1;
            smw[W_ACT_L + wi + 8 * ASTR] = l1;
        }

        uint32_t a2h[32], a2l[32];
        {
            const int r0w = rowbase + qid;
#pragma unroll
            for (int kt = 0; kt < 8; kt++) {
                int b0 = r0w + kt * 8;
                a2h[kt * 4 + 0] = smw[W_ACT_H + b0];
                a2h[kt * 4 + 1] = smw[W_ACT_H + b0 + 8 * ASTR];
                a2h[kt * 4 + 2] = smw[W_ACT_H + b0 + 4];
                a2h[kt * 4 + 3] = smw[W_ACT_H + b0 + 8 * ASTR + 4];
                a2l[kt * 4 + 0] = smw[W_ACT_L + b0];
                a2l[kt * 4 + 1] = smw[W_ACT_L + b0 + 8 * ASTR];
                a2l[kt * 4 + 2] = smw[W_ACT_L + b0 + 4];
                a2l[kt * 4 + 3] = smw[W_ACT_L + b0 + 8 * ASTR + 4];
            }
        }
        const int r0 = tile * 128 + w * 16 + grp;
        const float m0 = (r0 < N) ? 1.f : 0.f;
        const float m1 = (r0 + 8 < N) ? 1.f : 0.f;

#pragma unroll
        for (int nt = 0; nt < 8; nt++) {
            float c[4] = {0.f, 0.f, 0.f, 0.f};
            const int base = nt * 8 * WSTR + bq;
#pragma unroll
            for (int kt = 0; kt < 8; kt++) {
                int o = base + kt * 8;
                uint32_t bh0 = smw[W_W2_HI + o], bh1 = smw[W_W2_HI + o + 4];
                uint32_t bl0 = smw[W_W2_LO + o], bl1 = smw[W_W2_LO + o + 4];
                MMA_BF16(c, a2h[kt*4], a2h[kt*4+1], a2h[kt*4+2], a2h[kt*4+3], bh0, bh1);
                MMA_BF16(c, a2l[kt*4], a2l[kt*4+1], a2l[kt*4+2], a2l[kt*4+3], bh0, bh1);
                MMA_BF16(c, a2h[kt*4], a2h[kt*4+1], a2h[kt*4+2], a2h[kt*4+3], bl0, bl1);
            }
            accs[nt * 2]     += m0 * c[0] + m1 * c[2];
            accs[nt * 2 + 1] += m0 * c[1] + m1 * c[3];
        }
        __syncthreads();
    }

#pragma unroll
    for (int i = 0; i < 16; i++) {
        accs[i] += __shfl_xor_sync(0xffffffffu, accs[i], 4);
        accs[i] += __shfl_xor_sync(0xffffffffu, accs[i], 8);
        accs[i] += __shfl_xor_sync(0xffffffffu, accs[i], 16);
    }
    if (l < 4) {
#pragma unroll
        for (int nt = 0; nt < 8; nt++) {
            smf[W_RED + w * 64 + nt * 8 + 2 * l]     = accs[nt * 2];
            smf[W_RED + w * 64 + nt * 8 + 2 * l + 1] = accs[nt * 2 + 1];
        }
    }
    __syncthreads();
    if (t < 64) {
        float s = 0.f;
#pragma unroll
        for (int ww = 0; ww < 8; ww++) s += smf[W_RED + ww * 64 + t];
        g_wpart[blockIdx.x * 64 + t] = s;
    }
}

// ===========================================================================
// NODE kernel: block-phase; GEMM1 1-term bf16 with exact fp32 hid offset;
// GEMM2 3-term; reduces g_wpart.
// ===========================================================================
#define N_W1    0
#define N_W2_HI 8704
#define N_W2_LO 13056
#define N_ACT_H 17408
#define N_ACT_L 27136
#define N_HOFF  36864
#define N_WS    36992
#define N_WORDS 37056
#define N_BYTES (N_WORDS * 4)

__global__ void __launch_bounds__(256, 1)
node_mma_kernel(const float* __restrict__ z_h,
                const float* __restrict__ Wn1, const float* __restrict__ bn1,
                const float* __restrict__ Wn2, const float* __restrict__ bn2,
                const float* __restrict__ bw2,
                float* __restrict__ out, int N, int nwblocks) {
    extern __shared__ uint32_t smw[];
    float* smf = (float*)smw;
    uint16_t* smh = (uint16_t*)smw;

    const int t = threadIdx.x;
    const int w = t >> 5;
    const int l = t & 31;
    const int grp = l >> 2;
    const int qid = l & 3;

    for (int idx = t; idx < 128 * 128; idx += 256) {
        int k = idx >> 7, n = idx & 127;
        smh[(N_W1 + n * WSTR) * 2 + k] = __bfloat16_as_ushort(__float2bfloat16(Wn1[idx]));
    }
    for (int idx = t; idx < 128 * 64; idx += 256) {
        int k = idx >> 6, n = idx & 63;
        float v = Wn2[idx];
        __nv_bfloat16 h = __float2bfloat16(v);
        float r = v - __bfloat162float(h);
        smh[(N_W2_HI + n * WSTR) * 2 + k] = __bfloat16_as_ushort(h);
        smh[(N_W2_LO + n * WSTR) * 2 + k] = __bfloat16_as_ushort(__float2bfloat16(r));
    }
    if (t < 64) {
        float s = (float)N * __ldg(&bw2[t]);
        for (int b = 0; b < nwblocks; b++) s += g_wpart[b * 64 + t];
        smf[N_WS + t] = s;
    }
    __syncthreads();
    if (t < 128) {
        float acc = __ldg(&bn1[t]);
#pragma unroll 4
        for (int k = 0; k < 64; k++)
            acc = fmaf(smf[N_WS + k], __ldg(&Wn1[(64 + k) * 128 + t]), acc);
        smf[N_HOFF + t] = acc;
    }
    __syncthreads();

    const int ntiles = (N + 127) / 128;
    const int bq = grp * WSTR + qid;

    for (int tile = blockIdx.x; tile < ntiles; tile += gridDim.x) {
        {
            int e = t >> 1, half = t & 1;
            int n = tile * 128 + e;
            bool v = (n < N);
            const float4* srcp = half
                ? (const float4*)(g_magg + (size_t)(v ? n : 0) * 64)
                : (const float4*)(z_h + (size_t)(v ? n : 0) * 64);
            uint32_t* rh = smw + N_ACT_H + e * ASTR + half * 32;
#pragma unroll
            for (int q = 0; q < 16; q++) {
                float4 x = srcp[q];
                if (!v) x = make_float4(0.f, 0.f, 0.f, 0.f);
                rh[2 * q] = pack_hi(x.x, x.y);
                rh[2 * q + 1] = pack_hi(x.z, x.w);
            }
        }
        __syncthreads();

        uint32_t a1h[32];
        {
            const int r0w = (w * 16 + grp) * ASTR + qid;
#pragma unroll
            for (int kt = 0; kt < 8; kt++) {
                int b0 = r0w + kt * 8;
                a1h[kt * 4 + 0] = smw[N_ACT_H + b0];
                a1h[kt * 4 + 1] = smw[N_ACT_H + b0 + 8 * ASTR];
                a1h[kt * 4 + 2] = smw[N_ACT_H + b0 + 4];
                a1h[kt * 4 + 3] = smw[N_ACT_H + b0 + 8 * ASTR + 4];
            }
        }
        __syncthreads();

        const int rowbase = (w * 16 + grp) * ASTR;

#pragma unroll
        for (int nt2 = 0; nt2 < 8; nt2++) {
            const int ntA = nt2 * 2, ntB = ntA + 1;
            float cA[4] = {0.f, 0.f, 0.f, 0.f};
            float cB[4] = {0.f, 0.f, 0.f, 0.f};
            const int baseA = ntA * 8 * WSTR + bq;
            const int baseB = ntB * 8 * WSTR + bq;
#pragma unroll
            for (int kt = 0; kt < 8; kt++) {
                int oA = baseA + kt * 8, oB = baseB + kt * 8;
                uint32_t bA0 = smw[N_W1 + oA], bA1 = smw[N_W1 + oA + 4];
                uint32_t bB0 = smw[N_W1 + oB], bB1 = smw[N_W1 + oB + 4];
                MMA_BF16(cA, a1h[kt*4], a1h[kt*4+1], a1h[kt*4+2], a1h[kt*4+3], bA0, bA1);
                MMA_BF16(cB, a1h[kt*4], a1h[kt*4+1], a1h[kt*4+2], a1h[kt*4+3], bB0, bB1);
            }
#pragma unroll
            for (int s = 0; s < 2; s++) {
                const float* c = s ? cB : cA;
                const int nt = s ? ntB : ntA;
                const int n0 = nt * 8 + 2 * qid;
                const float h0v = smf[N_HOFF + n0], h1v = smf[N_HOFF + n0 + 1];
                float v0 = fmaxf(c[0] + h0v, 0.f);
                float v1 = fmaxf(c[1] + h1v, 0.f);
                float v2 = fmaxf(c[2] + h0v, 0.f);
                float v3 = fmaxf(c[3] + h1v, 0.f);
                uint32_t hh0, ll0, hh1, ll1;
                pack_pair(v0, v1, hh0, ll0);
                pack_pair(v2, v3, hh1, ll1);
                int wi = rowbase + nt * 4 + qid;
                smw[N_ACT_H + wi] = hh0;
                smw[N_ACT_L + wi] = ll0;
                smw[N_ACT_H + wi + 8 * ASTR] = hh1;
                smw[N_ACT_L + wi + 8 * ASTR] = ll1;
            }
        }
        __syncwarp();

        uint32_t a2h[32], a2l[32];
        {
            const int r0w = rowbase + qid;
#pragma unroll
            for (int kt = 0; kt < 8; kt++) {
                int b0 = r0w + kt * 8;
                a2h[kt * 4 + 0] = smw[N_ACT_H + b0];
                a2h[kt * 4 + 1] = smw[N_ACT_H + b0 + 8 * ASTR];
                a2h[kt * 4 + 2] = smw[N_ACT_H + b0 + 4];
                a2h[kt * 4 + 3] = smw[N_ACT_H + b0 + 8 * ASTR + 4];
                a2l[kt * 4 + 0] = smw[N_ACT_L + b0];
                a2l[kt * 4 + 1] = smw[N_ACT_L + b0 + 8 * ASTR];
                a2l[kt * 4 + 2] = smw[N_ACT_L + b0 + 4];
                a2l[kt * 4 + 3] = smw[N_ACT_L + b0 + 8 * ASTR + 4];
            }
        }
        const int r0 = tile * 128 + w * 16 + grp;
        const int r1 = r0 + 8;

#pragma unroll
        for (int nt = 0; nt < 8; nt++) {
            float c[4] = {0.f, 0.f, 0.f, 0.f};
            const int base = nt * 8 * WSTR + bq;
#pragma unroll
            for (int kt = 0; kt < 8; kt++) {
                int o = base + kt * 8;
                uint32_t bh0 = smw[N_W2_HI + o], bh1 = smw[N_W2_HI + o + 4];
                uint32_t bl0 = smw[N_W2_LO + o], bl1 = smw[N_W2_LO + o + 4];
                MMA_BF16(c, a2h[kt*4], a2h[kt*4+1], a2h[kt*4+2], a2h[kt*4+3], bh0, bh1);
                MMA_BF16(c, a2l[kt*4], a2l[kt*4+1], a2l[kt*4+2], a2l[kt*4+3], bh0, bh1);
                MMA_BF16(c, a2h[kt*4], a2h[kt*4+1], a2h[kt*4+2], a2h[kt*4+3], bl0, bl1);
            }
            int n0 = nt * 8 + 2 * qid;
            float b0v = __ldg(&bn2[n0]), b1v = __ldg(&bn2[n0 + 1]);
            if (r0 < N) {
                float2 o2 = make_float2(c[0] + b0v, c[1] + b1v);
                *(float2*)(out + (size_t)r0 * 64 + n0) = o2;
            }
            if (r1 < N) {
                float2 o2 = make_float2(c[2] + b0v, c[3] + b1v);
                *(float2*)(out + (size_t)r1 * 64 + n0) = o2;
            }
        }
        __syncthreads();
    }
}

// ===========================================================================
extern "C" void kernel_launch(void* const* d_in, const int* in_sizes, int n_in,
                              void* d_out, int out_size) {
    const float* z_h       = (const float*)d_in[0];
    const float* pos_world = (const float*)d_in[1];
    const int*   ei        = (const int*)d_in[2];
    const float* We1 = (const float*)d_in[3];
    const float* be1 = (const float*)d_in[4];
    const float* We2 = (const float*)d_in[5];
    const float* be2 = (const float*)d_in[6];
    const float* Wg1 = (const float*)d_in[7];
    const float* bg1 = (const float*)d_in[8];
    const float* Wg2 = (const float*)d_in[9];
    const float* bg2 = (const float*)d_in[10];
    const float* Wn1 = (const float*)d_in[11];
    const float* bn1 = (const float*)d_in[12];
    const float* Wn2 = (const float*)d_in[13];
    const float* bn2 = (const float*)d_in[14];
    const float* Ww1 = (const float*)d_in[15];
    const float* bw1 = (const float*)d_in[16];
    const float* Ww2 = (const float*)d_in[17];
    const float* bw2 = (const float*)d_in[18];

    const int N = in_sizes[0] / 64;
    const int E = in_sizes[2] / 2;
    float* out = (float*)d_out;

    cudaFuncSetAttribute(edge_mma_kernel,
                         cudaFuncAttributeMaxDynamicSharedMemorySize, E_BYTES);
    cudaFuncSetAttribute(node_mma_kernel,
                         cudaFuncAttributeMaxDynamicSharedMemorySize, N_BYTES);
    cudaFuncSetAttribute(world_mma_kernel,
                         cudaFuncAttributeMaxDynamicSharedMemorySize, W_BYTES);

    const int NWB = 148;
    world_mma_kernel<<<NWB, 256, W_BYTES>>>(z_h, pos_world, Ww1, bw1, Ww2, N);
    edge_mma_kernel<<<148, ETHREADS, E_BYTES>>>(ei, We1, be1, We2, be2,
                                                Wg1, bg1, Wg2, bg2, E);
    node_mma_kernel<<<148, 256, N_BYTES>>>(z_h, Wn1, bn1, Wn2, bn2, bw2,
                                           out, N, NWB);
}

// round 17
// speedup vs baseline: 1.0147x; 1.0033x over previous
#include <cuda_runtime.h>
#include <cuda_bf16.h>
#include <math.h>
#include <stdint.h>

// ===========================================================================
// Scratch (no allocations allowed)
// ===========================================================================
__device__ float g_magg[50048 * 64];
__device__ float g_wpart[148 * 64];
__device__ uint32_t g_zpk[50048 * 32];   // prepacked bf16x2 z_h

// ===========================================================================
// warp MMA m16n8k16 bf16 (sm_80+ PTX, no arch suffix)
// ===========================================================================
#define MMA_BF16(c, a0, a1, a2, a3, b0, b1) \
    asm volatile("mma.sync.aligned.m16n8k16.row.col.f32.bf16.bf16.f32 " \
        "{%0,%1,%2,%3},{%4,%5,%6,%7},{%8,%9},{%0,%1,%2,%3};" \
        : "+f"((c)[0]), "+f"((c)[1]), "+f"((c)[2]), "+f"((c)[3]) \
        : "r"(a0), "r"(a1), "r"(a2), "r"(a3), "r"(b0), "r"(b1))

__device__ __forceinline__ void red_add_v4(float* addr, float x, float y, float z, float w_) {
    asm volatile("red.global.add.v4.f32 [%0], {%1, %2, %3, %4};"
                 :: "l"(addr), "f"(x), "f"(y), "f"(z), "f"(w_) : "memory");
}

__device__ __forceinline__ uint32_t pack_hi(float v0, float v1) {
    return ((uint32_t)__bfloat16_as_ushort(__float2bfloat16(v1)) << 16) |
           (uint32_t)__bfloat16_as_ushort(__float2bfloat16(v0));
}

__device__ __forceinline__ void pack_pair(float v0, float v1, uint32_t& hi, uint32_t& lo) {
    __nv_bfloat16 h0 = __float2bfloat16(v0);
    __nv_bfloat16 h1 = __float2bfloat16(v1);
    float r0 = v0 - __bfloat162float(h0);
    float r1 = v1 - __bfloat162float(h1);
    hi = ((uint32_t)__bfloat16_as_ushort(h1) << 16) | (uint32_t)__bfloat16_as_ushort(h0);
    lo = ((uint32_t)__bfloat16_as_ushort(__float2bfloat16(r1)) << 16) |
         (uint32_t)__bfloat16_as_ushort(__float2bfloat16(r0));
}

__device__ __forceinline__ float bf_lo(uint32_t u) {
    return __bfloat162float(__ushort_as_bfloat16((unsigned short)(u & 0xffffu)));
}
__device__ __forceinline__ float bf_hi(uint32_t u) {
    return __bfloat162float(__ushort_as_bfloat16((unsigned short)(u >> 16)));
}

#define ASTR 76   // activation row stride, words (mod32=12, conflict-free)
#define WSTR 68   // weight row stride, words (mod32=4, conflict-free)

// ===========================================================================
// EDGE kernel: 12 warps x 32-edge units, 1-term bf16 weights,
// separate msg/gate passes, red.v4 scatter (measured best ~276us).
// ===========================================================================
#define ETHREADS 384
#define EWARPS   12

#define E_W1E   0
#define E_W1G   8704
#define E_W2    17408
#define E_ACT   21760
#define E_TGT   50944
#define E_GATE  51328
#define E_BE1   51712
#define E_BG1   51840
#define E_WG2   51968
#define E_BE2   52096
#define E_WORDS 52160
#define E_BYTES (E_WORDS * 4)

__global__ void __launch_bounds__(ETHREADS, 1)
edge_mma_kernel(const int* __restrict__ ei,
                const float* __restrict__ We1, const float* __restrict__ be1,
                const float* __restrict__ We2, const float* __restrict__ be2,
                const float* __restrict__ Wg1, const float* __restrict__ bg1,
                const float* __restrict__ Wg2, const float* __restrict__ bg2,
                int E) {
    extern __shared__ uint32_t smw[];
    float* smf = (float*)smw;
    int* smi = (int*)smw;
    uint16_t* smh = (uint16_t*)smw;

    const int t = threadIdx.x;
    const int w = t >> 5;
    const int l = t & 31;
    const int grp = l >> 2;
    const int qid = l & 3;

    for (int idx = t; idx < 136 * 128; idx += ETHREADS) {
        int k = idx >> 7, n = idx & 127;
        smh[(E_W1E + n * WSTR) * 2 + k] = __bfloat16_as_ushort(__float2bfloat16(We1[idx]));
        smh[(E_W1G + n * WSTR) * 2 + k] = __bfloat16_as_ushort(__float2bfloat16(Wg1[idx]));
    }
    for (int idx = t; idx < 128 * 64; idx += ETHREADS) {
        int k = idx >> 6, n = idx & 63;
        smh[(E_W2 + n * WSTR) * 2 + k] = __bfloat16_as_ushort(__float2bfloat16(We2[idx]));
    }
    if (t < 128) {
        smf[E_BE1 + t] = be1[t];
        smf[E_BG1 + t] = bg1[t];
        smf[E_WG2 + t] = Wg2[t];
    }
    if (t < 64) smf[E_BE2 + t] = be2[t];
    const float bg2v = __ldg(&bg2[0]);
    __syncthreads();

    const int nunits = (E + 31) / 32;
    const int bq = grp * WSTR + qid;
    const int e_local = w * 32 + l;
    uint32_t* const myrow = smw + E_ACT + e_local * ASTR;
    const int rowbase = (w * 32 + grp) * ASTR;
    const int row0 = w * 32 + grp;

    for (int unit = blockIdx.x * EWARPS + w; unit < nunits; unit += gridDim.x * EWARPS) {
        const int eg = unit * 32 + l;
        const int sN = (eg < E) ? ei[eg] : 0;
        const int tN = (eg < E) ? ei[E + eg] : 0;
        smi[E_TGT + e_local] = tN;
        const uint4* zs = (const uint4*)(g_zpk + (size_t)sN * 32);
        const uint4* zt = (const uint4*)(g_zpk + (size_t)tN * 32);
        uint4 s0 = zs[0];
        uint4 t0 = zt[0];
        myrow[0] = s0.x; myrow[1] = s0.y; myrow[2] = s0.z; myrow[3] = s0.w;
        myrow[32] = t0.x; myrow[33] = t0.y; myrow[34] = t0.z; myrow[35] = t0.w;
#pragma unroll
        for (int q = 1; q < 8; q++) {
            uint4 v = zs[q];
            myrow[4 * q] = v.x; myrow[4 * q + 1] = v.y;
            myrow[4 * q + 2] = v.z; myrow[4 * q + 3] = v.w;
        }
#pragma unroll
        for (int q = 1; q < 8; q++) {
            uint4 v = zt[q];
            myrow[32 + 4 * q] = v.x; myrow[33 + 4 * q] = v.y;
            myrow[34 + 4 * q] = v.z; myrow[35 + 4 * q] = v.w;
        }
        {
            float a0 = bf_lo(s0.x), a1 = bf_hi(s0.x), a2 = bf_lo(s0.y);
            float a3 = bf_hi(s0.y), a4 = bf_lo(s0.z), a5 = bf_hi(s0.z);
            float b0 = bf_lo(t0.x), b1 = bf_hi(t0.x), b2 = bf_lo(t0.y);
            float b3 = bf_hi(t0.y), b4 = bf_lo(t0.z), b5 = bf_hi(t0.z);
            float dx = a0 - b0, dy = a1 - b1, dz = a2 - b2;
            float dist = dx * dx + dy * dy + dz * dz;
            float cx = a4 * b5 - a5 * b4;
            float cy = a5 * b3 - a3 * b5;
            float cz = a3 * b4 - a4 * b3;
            float cn = sqrtf(cx * cx + cy * cy + cz * cz);
            myrow[64] = pack_hi(dx, dy);
            myrow[65] = pack_hi(dz, dist);
            myrow[66] = pack_hi(cx, cy);
            myrow[67] = pack_hi(cz, cn);
            myrow[68] = 0; myrow[69] = 0; myrow[70] = 0; myrow[71] = 0;
        }
        __syncwarp();

        uint32_t a1h[72];
        {
            const int r0w = rowbase + qid;
#pragma unroll
            for (int kt = 0; kt < 9; kt++) {
                int b0 = r0w + kt * 8;
                a1h[kt * 8 + 0] = smw[E_ACT + b0];
                a1h[kt * 8 + 1] = smw[E_ACT + b0 + 8 * ASTR];
                a1h[kt * 8 + 2] = smw[E_ACT + b0 + 4];
                a1h[kt * 8 + 3] = smw[E_ACT + b0 + 8 * ASTR + 4];
                a1h[kt * 8 + 4] = smw[E_ACT + b0 + 16 * ASTR];
                a1h[kt * 8 + 5] = smw[E_ACT + b0 + 24 * ASTR];
                a1h[kt * 8 + 6] = smw[E_ACT + b0 + 16 * ASTR + 4];
                a1h[kt * 8 + 7] = smw[E_ACT + b0 + 24 * ASTR + 4];
            }
        }
        __syncwarp();

#pragma unroll
        for (int nt = 0; nt < 16; nt++) {
            float c0[4] = {0.f, 0.f, 0.f, 0.f};
            float c1[4] = {0.f, 0.f, 0.f, 0.f};
            const int base = nt * 8 * WSTR + bq;
#pragma unroll
            for (int kt = 0; kt < 9; kt++) {
                int o = base + kt * 8;
                uint32_t b0 = smw[E_W1E + o], b1 = smw[E_W1E + o + 4];
                MMA_BF16(c0, a1h[kt*8+0], a1h[kt*8+1], a1h[kt*8+2], a1h[kt*8+3], b0, b1);
                MMA_BF16(c1, a1h[kt*8+4], a1h[kt*8+5], a1h[kt*8+6], a1h[kt*8+7], b0, b1);
            }
            const int n0 = nt * 8 + 2 * qid;
            const float be0 = smf[E_BE1 + n0], be1v = smf[E_BE1 + n0 + 1];
            const int wi = rowbase + nt * 4 + qid;
            smw[E_ACT + wi] =
                pack_hi(fmaxf(c0[0] + be0, 0.f), fmaxf(c0[1] + be1v, 0.f));
            smw[E_ACT + wi + 8 * ASTR] =
                pack_hi(fmaxf(c0[2] + be0, 0.f), fmaxf(c0[3] + be1v, 0.f));
            smw[E_ACT + wi + 16 * ASTR] =
                pack_hi(fmaxf(c1[0] + be0, 0.f), fmaxf(c1[1] + be1v, 0.f));
            smw[E_ACT + wi + 24 * ASTR] =
                pack_hi(fmaxf(c1[2] + be0, 0.f), fmaxf(c1[3] + be1v, 0.f));
        }

        float ps[4] = {0.f, 0.f, 0.f, 0.f};
#pragma unroll
        for (int nt = 0; nt < 16; nt++) {
            float c0[4] = {0.f, 0.f, 0.f, 0.f};
            float c1[4] = {0.f, 0.f, 0.f, 0.f};
            const int base = nt * 8 * WSTR + bq;
#pragma unroll
            for (int kt = 0; kt < 9; kt++) {
                int o = base + kt * 8;
                uint32_t b0 = smw[E_W1G + o], b1 = smw[E_W1G + o + 4];
                MMA_BF16(c0, a1h[kt*8+0], a1h[kt*8+1], a1h[kt*8+2], a1h[kt*8+3], b0, b1);
                MMA_BF16(c1, a1h[kt*8+4], a1h[kt*8+5], a1h[kt*8+6], a1h[kt*8+7], b0, b1);
            }
            const int n0 = nt * 8 + 2 * qid;
            const float w0 = smf[E_WG2 + n0], w1 = smf[E_WG2 + n0 + 1];
            const float b0v = smf[E_BG1 + n0], b1v = smf[E_BG1 + n0 + 1];
            ps[0] += fmaxf(c0[0] + b0v, 0.f) * w0 + fmaxf(c0[1] + b1v, 0.f) * w1;
            ps[1] += fmaxf(c0[2] + b0v, 0.f) * w0 + fmaxf(c0[3] + b1v, 0.f) * w1;
            ps[2] += fmaxf(c1[0] + b0v, 0.f) * w0 + fmaxf(c1[1] + b1v, 0.f) * w1;
            ps[3] += fmaxf(c1[2] + b0v, 0.f) * w0 + fmaxf(c1[3] + b1v, 0.f) * w1;
        }
#pragma unroll
        for (int i = 0; i < 4; i++) {
            ps[i] += __shfl_xor_sync(0xffffffffu, ps[i], 1);
            ps[i] += __shfl_xor_sync(0xffffffffu, ps[i], 2);
        }
        if (qid == 0) {
            smf[E_GATE + row0]      = 1.f / (1.f + __expf(-(ps[0] + bg2v)));
            smf[E_GATE + row0 + 8]  = 1.f / (1.f + __expf(-(ps[1] + bg2v)));
            smf[E_GATE + row0 + 16] = 1.f / (1.f + __expf(-(ps[2] + bg2v)));
            smf[E_GATE + row0 + 24] = 1.f / (1.f + __expf(-(ps[3] + bg2v)));
        }
        __syncwarp();

        uint32_t a2h[64];
        {
            const int r0w = rowbase + qid;
#pragma unroll
            for (int kt = 0; kt < 8; kt++) {
                int b0 = r0w + kt * 8;
                a2h[kt * 8 + 0] = smw[E_ACT + b0];
                a2h[kt * 8 + 1] = smw[E_ACT + b0 + 8 * ASTR];
                a2h[kt * 8 + 2] = smw[E_ACT + b0 + 4];
                a2h[kt * 8 + 3] = smw[E_ACT + b0 + 8 * ASTR + 4];
                a2h[kt * 8 + 4] = smw[E_ACT + b0 + 16 * ASTR];
                a2h[kt * 8 + 5] = smw[E_ACT + b0 + 24 * ASTR];
                a2h[kt * 8 + 6] = smw[E_ACT + b0 + 16 * ASTR + 4];
                a2h[kt * 8 + 7] = smw[E_ACT + b0 + 24 * ASTR + 4];
            }
        }
        __syncwarp();

        const float g0 = smf[E_GATE + row0];
        const float g1 = smf[E_GATE + row0 + 8];
        const float g2 = smf[E_GATE + row0 + 16];
        const float g3 = smf[E_GATE + row0 + 24];

#pragma unroll
        for (int nt = 0; nt < 8; nt++) {
            float c0[4] = {0.f, 0.f, 0.f, 0.f};
            float c1[4] = {0.f, 0.f, 0.f, 0.f};
            const int base = nt * 8 * WSTR + bq;
#pragma unroll
            for (int kt = 0; kt < 8; kt++) {
                int o = base + kt * 8;
                uint32_t b0 = smw[E_W2 + o], b1 = smw[E_W2 + o + 4];
                MMA_BF16(c0, a2h[kt*8+0], a2h[kt*8+1], a2h[kt*8+2], a2h[kt*8+3], b0, b1);
                MMA_BF16(c1, a2h[kt*8+4], a2h[kt*8+5], a2h[kt*8+6], a2h[kt*8+7], b0, b1);
            }
            const int n0 = nt * 8 + 2 * qid;
            const float b0v = smf[E_BE2 + n0], b1v = smf[E_BE2 + n0 + 1];
            *(float2*)&smf[E_ACT + rowbase + n0] =
                make_float2(g0 * (c0[0] + b0v), g0 * (c0[1] + b1v));
            *(float2*)&smf[E_ACT + rowbase + 8 * ASTR + n0] =
                make_float2(g1 * (c0[2] + b0v), g1 * (c0[3] + b1v));
            *(float2*)&smf[E_ACT + rowbase + 16 * ASTR + n0] =
                make_float2(g2 * (c1[0] + b0v), g2 * (c1[1] + b1v));
            *(float2*)&smf[E_ACT + rowbase + 24 * ASTR + n0] =
                make_float2(g3 * (c1[2] + b0v), g3 * (c1[3] + b1v));
        }
        __syncwarp();

#pragma unroll
        for (int it = 0; it < 16; it++) {
            const int j = it * 32 + l;
            const int er = j >> 4;
            const int ch = j & 15;
            const int eglobal = unit * 32 + er;
            if (eglobal < E) {
                const int tg = smi[E_TGT + w * 32 + er];
                const float4 v = *(const float4*)&smf[E_ACT + (w * 32 + er) * ASTR + ch * 4];
                red_add_v4(g_magg + (size_t)tg * 64 + ch * 4, v.x, v.y, v.z, v.w);
            }
        }
        __syncwarp();
    }
}

// ===========================================================================
// WORLD kernel: block-phase; absorbs init; 3-term bf16 MMA;
// per-block partials to g_wpart.
// ===========================================================================
#define W_W1_HI 0
#define W_W1_LO 8704
#define W_W2_HI 17408
#define W_W2_LO 21760
#define W_ACT_H 26112
#define W_ACT_L 35840
#define W_BW1   45568
#define W_RED   45696
#define W_WORDS 46208
#define W_BYTES (W_WORDS * 4)

__global__ void __launch_bounds__(256, 1)
world_mma_kernel(const float* __restrict__ z_h, const float* __restrict__ pos_world,
                 const float* __restrict__ Ww1, const float* __restrict__ bw1,
                 const float* __restrict__ Ww2, int N) {
    extern __shared__ uint32_t smw[];
    float* smf = (float*)smw;
    uint16_t* smh = (uint16_t*)smw;

    const int t = threadIdx.x;
    const int w = t >> 5;
    const int l = t & 31;
    const int grp = l >> 2;
    const int qid = l & 3;

    // ---- init: zero g_magg + prepack z_h ----
    {
        const int nmag4 = (N * 64) >> 2;
        float4 z4 = make_float4(0.f, 0.f, 0.f, 0.f);
        for (int i = blockIdx.x * 256 + t; i < nmag4; i += gridDim.x * 256)
            ((float4*)g_magg)[i] = z4;
        const int npk = N * 32;
        for (int i = blockIdx.x * 256 + t; i < npk; i += gridDim.x * 256) {
            float2 v = ((const float2*)z_h)[i];
            g_zpk[i] = pack_hi(v.x, v.y);
        }
    }

    for (int i = t; i < 17408; i += 256) smw[W_W1_HI + i] = 0;
    __syncthreads();
    for (int idx = t; idx < 67 * 128; idx += 256) {
        int k = idx >> 7, n = idx & 127;
        float v = Ww1[idx];
        __nv_bfloat16 h = __float2bfloat16(v);
        float r = v - __bfloat162float(h);
        smh[(W_W1_HI + n * WSTR) * 2 + k] = __bfloat16_as_ushort(h);
        smh[(W_W1_LO + n * WSTR) * 2 + k] = __bfloat16_as_ushort(__float2bfloat16(r));
    }
    for (int idx = t; idx < 128 * 64; idx += 256) {
        int k = idx >> 6, n = idx & 63;
        float v = Ww2[idx];
        __nv_bfloat16 h = __float2bfloat16(v);
        float r = v - __bfloat162float(h);
        smh[(W_W2_HI + n * WSTR) * 2 + k] = __bfloat16_as_ushort(h);
        smh[(W_W2_LO + n * WSTR) * 2 + k] = __bfloat16_as_ushort(__float2bfloat16(r));
    }
    if (t < 128) smf[W_BW1 + t] = bw1[t];
    const float p0 = __ldg(&pos_world[0]);
    const float p1 = __ldg(&pos_world[1]);
    const float p2 = __ldg(&pos_world[2]);
    __syncthreads();

    const int ntiles = (N + 127) / 128;
    const int bq = grp * WSTR + qid;

    float accs[16];
#pragma unroll
    for (int i = 0; i < 16; i++) accs[i] = 0.f;

    for (int tile = blockIdx.x; tile < ntiles; tile += gridDim.x) {
        {
            int e = t >> 1, half = t & 1;
            int n = tile * 128 + e;
            bool v = (n < N);
            const float4* zp = (const float4*)(z_h + (size_t)(v ? n : 0) * 64) + half * 8;
            uint32_t* rh = smw + W_ACT_H + e * ASTR + half * 16;
            uint32_t* rl = smw + W_ACT_L + e * ASTR + half * 16;
#pragma unroll
            for (int q = 0; q < 8; q++) {
                float4 x = zp[q];
                if (!v) x = make_float4(0.f, 0.f, 0.f, 0.f);
                uint32_t h0, l0, h1, l1;
                pack_pair(x.x, x.y, h0, l0);
                pack_pair(x.z, x.w, h1, l1);
                rh[2 * q] = h0; rh[2 * q + 1] = h1;
                rl[2 * q] = l0; rl[2 * q + 1] = l1;
            }
        }
        if (t < 128) {
            int n = tile * 128 + t;
            bool v = (n < N);
            float4 z0 = *(const float4*)(z_h + (size_t)(v ? n : 0) * 64);
            float d0 = v ? z0.x - p0 : 0.f;
            float d1 = v ? z0.y - p1 : 0.f;
            float d2 = v ? z0.z - p2 : 0.f;
            uint32_t* rh = smw + W_ACT_H + t * ASTR + 32;
            uint32_t* rl = smw + W_ACT_L + t * ASTR + 32;
            uint32_t h0, l0, h1, l1;
            pack_pair(d0, d1, h0, l0);
            pack_pair(d2, 0.f, h1, l1);
            rh[0] = h0; rl[0] = l0;
            rh[1] = h1; rl[1] = l1;
#pragma unroll
            for (int q = 2; q < 8; q++) { rh[q] = 0; rl[q] = 0; }
        }
        __syncthreads();

        uint32_t a1h[20], a1l[20];
        {
            const int r0w = (w * 16 + grp) * ASTR + qid;
#pragma unroll
            for (int kt = 0; kt < 5; kt++) {
                int b0 = r0w + kt * 8;
                a1h[kt * 4 + 0] = smw[W_ACT_H + b0];
                a1h[kt * 4 + 1] = smw[W_ACT_H + b0 + 8 * ASTR];
                a1h[kt * 4 + 2] = smw[W_ACT_H + b0 + 4];
                a1h[kt * 4 + 3] = smw[W_ACT_H + b0 + 8 * ASTR + 4];
                a1l[kt * 4 + 0] = smw[W_ACT_L + b0];
                a1l[kt * 4 + 1] = smw[W_ACT_L + b0 + 8 * ASTR];
                a1l[kt * 4 + 2] = smw[W_ACT_L + b0 + 4];
                a1l[kt * 4 + 3] = smw[W_ACT_L + b0 + 8 * ASTR + 4];
            }
        }
        __syncthreads();

        const int rowbase = (w * 16 + grp) * ASTR;

#pragma unroll
        for (int nt = 0; nt < 16; nt++) {
            float c[4] = {0.f, 0.f, 0.f, 0.f};
            const int base = nt * 8 * WSTR + bq;
#pragma unroll
            for (int kt = 0; kt < 5; kt++) {
                int o = base + kt * 8;
                uint32_t bh0 = smw[W_W1_HI + o], bh1 = smw[W_W1_HI + o + 4];
                uint32_t bl0 = smw[W_W1_LO + o], bl1 = smw[W_W1_LO + o + 4];
                MMA_BF16(c, a1h[kt*4], a1h[kt*4+1], a1h[kt*4+2], a1h[kt*4+3], bh0, bh1);
                MMA_BF16(c, a1l[kt*4], a1l[kt*4+1], a1l[kt*4+2], a1l[kt*4+3], bh0, bh1);
                MMA_BF16(c, a1h[kt*4], a1h[kt*4+1], a1h[kt*4+2], a1h[kt*4+3], bl0, bl1);
            }
            int n0 = nt * 8 + 2 * qid;
            float v0 = fmaxf(c[0] + smf[W_BW1 + n0], 0.f);
            float v1 = fmaxf(c[1] + smf[W_BW1 + n0 + 1], 0.f);
            float v2 = fmaxf(c[2] + smf[W_BW1 + n0], 0.f);
            float v3 = fmaxf(c[3] + smf[W_BW1 + n0 + 1], 0.f);
            uint32_t h0, l0, h1, l1;
            pack_pair(v0, v1, h0, l0);
            pack_pair(v2, v3, h1, l1);
            int wi = rowbase + nt * 4 + qid;
            smw[W_ACT_H + wi] = h0;
            smw[W_ACT_L + wi] = l0;
            smw[W_ACT_H + wi + 8 * ASTR] = h1;
            smw[W_ACT_L + wi + 8 * ASTR] = l1;
        }

        uint32_t a2h[32], a2l[32];
        {
            const int r0w = rowbase + qid;
#pragma unroll
            for (int kt = 0; kt < 8; kt++) {
                int b0 = r0w + kt * 8;
                a2h[kt * 4 + 0] = smw[W_ACT_H + b0];
                a2h[kt * 4 + 1] = smw[W_ACT_H + b0 + 8 * ASTR];
                a2h[kt * 4 + 2] = smw[W_ACT_H + b0 + 4];
                a2h[kt * 4 + 3] = smw[W_ACT_H + b0 + 8 * ASTR + 4];
                a2l[kt * 4 + 0] = smw[W_ACT_L + b0];
                a2l[kt * 4 + 1] = smw[W_ACT_L + b0 + 8 * ASTR];
                a2l[kt * 4 + 2] = smw[W_ACT_L + b0 + 4];
                a2l[kt * 4 + 3] = smw[W_ACT_L + b0 + 8 * ASTR + 4];
            }
        }
        const int r0 = tile * 128 + w * 16 + grp;
        const float m0 = (r0 < N) ? 1.f : 0.f;
        const float m1 = (r0 + 8 < N) ? 1.f : 0.f;

#pragma unroll
        for (int nt = 0; nt < 8; nt++) {
            float c[4] = {0.f, 0.f, 0.f, 0.f};
            const int base = nt * 8 * WSTR + bq;
#pragma unroll
            for (int kt = 0; kt < 8; kt++) {
                int o = base + kt * 8;
                uint32_t bh0 = smw[W_W2_HI + o], bh1 = smw[W_W2_HI + o + 4];
                uint32_t bl0 = smw[W_W2_LO + o], bl1 = smw[W_W2_LO + o + 4];
                MMA_BF16(c, a2h[kt*4], a2h[kt*4+1], a2h[kt*4+2], a2h[kt*4+3], bh0, bh1);
                MMA_BF16(c, a2l[kt*4], a2l[kt*4+1], a2l[kt*4+2], a2l[kt*4+3], bh0, bh1);
                MMA_BF16(c, a2h[kt*4], a2h[kt*4+1], a2h[kt*4+2], a2h[kt*4+3], bl0, bl1);
            }
            accs[nt * 2]     += m0 * c[0] + m1 * c[2];
            accs[nt * 2 + 1] += m0 * c[1] + m1 * c[3];
        }
        __syncthreads();
    }

#pragma unroll
    for (int i = 0; i < 16; i++) {
        accs[i] += __shfl_xor_sync(0xffffffffu, accs[i], 4);
        accs[i] += __shfl_xor_sync(0xffffffffu, accs[i], 8);
        accs[i] += __shfl_xor_sync(0xffffffffu, accs[i], 16);
    }
    if (l < 4) {
#pragma unroll
        for (int nt = 0; nt < 8; nt++) {
            smf[W_RED + w * 64 + nt * 8 + 2 * l]     = accs[nt * 2];
            smf[W_RED + w * 64 + nt * 8 + 2 * l + 1] = accs[nt * 2 + 1];
        }
    }
    __syncthreads();
    if (t < 64) {
        float s = 0.f;
#pragma unroll
        for (int ww = 0; ww < 8; ww++) s += smf[W_RED + ww * 64 + t];
        g_wpart[blockIdx.x * 64 + t] = s;
    }
}

// ===========================================================================
// NODE kernel: block-phase; GEMM1 1-term bf16 with exact fp32 hid offset;
// GEMM2 3-term; reduces g_wpart.
// ===========================================================================
#define N_W1    0
#define N_W2_HI 8704
#define N_W2_LO 13056
#define N_ACT_H 17408
#define N_ACT_L 27136
#define N_HOFF  36864
#define N_WS    36992
#define N_WORDS 37056
#define N_BYTES (N_WORDS * 4)

__global__ void __launch_bounds__(256, 1)
node_mma_kernel(const float* __restrict__ z_h,
                const float* __restrict__ Wn1, const float* __restrict__ bn1,
                const float* __restrict__ Wn2, const float* __restrict__ bn2,
                const float* __restrict__ bw2,
                float* __restrict__ out, int N, int nwblocks) {
    extern __shared__ uint32_t smw[];
    float* smf = (float*)smw;
    uint16_t* smh = (uint16_t*)smw;

    const int t = threadIdx.x;
    const int w = t >> 5;
    const int l = t & 31;
    const int grp = l >> 2;
    const int qid = l & 3;

    for (int idx = t; idx < 128 * 128; idx += 256) {
        int k = idx >> 7, n = idx & 127;
        smh[(N_W1 + n * WSTR) * 2 + k] = __bfloat16_as_ushort(__float2bfloat16(Wn1[idx]));
    }
    for (int idx = t; idx < 128 * 64; idx += 256) {
        int k = idx >> 6, n = idx & 63;
        float v = Wn2[idx];
        __nv_bfloat16 h = __float2bfloat16(v);
        float r = v - __bfloat162float(h);
        smh[(N_W2_HI + n * WSTR) * 2 + k] = __bfloat16_as_ushort(h);
        smh[(N_W2_LO + n * WSTR) * 2 + k] = __bfloat16_as_ushort(__float2bfloat16(r));
    }
    if (t < 64) {
        float s = (float)N * __ldg(&bw2[t]);
        for (int b = 0; b < nwblocks; b++) s += g_wpart[b * 64 + t];
        smf[N_WS + t] = s;
    }
    __syncthreads();
    if (t < 128) {
        float acc = __ldg(&bn1[t]);
#pragma unroll 4
        for (int k = 0; k < 64; k++)
            acc = fmaf(smf[N_WS + k], __ldg(&Wn1[(64 + k) * 128 + t]), acc);
        smf[N_HOFF + t] = acc;
    }
    __syncthreads();

    const int ntiles = (N + 127) / 128;
    const int bq = grp * WSTR + qid;

    for (int tile = blockIdx.x; tile < ntiles; tile += gridDim.x) {
        {
            int e = t >> 1, half = t & 1;
            int n = tile * 128 + e;
            bool v = (n < N);
            const float4* srcp = half
                ? (const float4*)(g_magg + (size_t)(v ? n : 0) * 64)
                : (const float4*)(z_h + (size_t)(v ? n : 0) * 64);
            uint32_t* rh = smw + N_ACT_H + e * ASTR + half * 32;
#pragma unroll
            for (int q = 0; q < 16; q++) {
                float4 x = srcp[q];
                if (!v) x = make_float4(0.f, 0.f, 0.f, 0.f);
                rh[2 * q] = pack_hi(x.x, x.y);
                rh[2 * q + 1] = pack_hi(x.z, x.w);
            }
        }
        __syncthreads();

        uint32_t a1h[32];
        {
            const int r0w = (w * 16 + grp) * ASTR + qid;
#pragma unroll
            for (int kt = 0; kt < 8; kt++) {
                int b0 = r0w + kt * 8;
                a1h[kt * 4 + 0] = smw[N_ACT_H + b0];
                a1h[kt * 4 + 1] = smw[N_ACT_H + b0 + 8 * ASTR];
                a1h[kt * 4 + 2] = smw[N_ACT_H + b0 + 4];
                a1h[kt * 4 + 3] = smw[N_ACT_H + b0 + 8 * ASTR + 4];
            }
        }
        __syncthreads();

        const int rowbase = (w * 16 + grp) * ASTR;

#pragma unroll
        for (int nt2 = 0; nt2 < 8; nt2++) {
            const int ntA = nt2 * 2, ntB = ntA + 1;
            float cA[4] = {0.f, 0.f, 0.f, 0.f};
            float cB[4] = {0.f, 0.f, 0.f, 0.f};
            const int baseA = ntA * 8 * WSTR + bq;
            const int baseB = ntB * 8 * WSTR + bq;
#pragma unroll
            for (int kt = 0; kt < 8; kt++) {
                int oA = baseA + kt * 8, oB = baseB + kt * 8;
                uint32_t bA0 = smw[N_W1 + oA], bA1 = smw[N_W1 + oA + 4];
                uint32_t bB0 = smw[N_W1 + oB], bB1 = smw[N_W1 + oB + 4];
                MMA_BF16(cA, a1h[kt*4], a1h[kt*4+1], a1h[kt*4+2], a1h[kt*4+3], bA0, bA1);
                MMA_BF16(cB, a1h[kt*4], a1h[kt*4+1], a1h[kt*4+2], a1h[kt*4+3], bB0, bB1);
            }
#pragma unroll
            for (int s = 0; s < 2; s++) {
                const float* c = s ? cB : cA;
                const int nt = s ? ntB : ntA;
                const int n0 = nt * 8 + 2 * qid;
                const float h0v = smf[N_HOFF + n0], h1v = smf[N_HOFF + n0 + 1];
                float v0 = fmaxf(c[0] + h0v, 0.f);
                float v1 = fmaxf(c[1] + h1v, 0.f);
                float v2 = fmaxf(c[2] + h0v, 0.f);
                float v3 = fmaxf(c[3] + h1v, 0.f);
                uint32_t hh0, ll0, hh1, ll1;
                pack_pair(v0, v1, hh0, ll0);
                pack_pair(v2, v3, hh1, ll1);
                int wi = rowbase + nt * 4 + qid;
                smw[N_ACT_H + wi] = hh0;
                smw[N_ACT_L + wi] = ll0;
                smw[N_ACT_H + wi + 8 * ASTR] = hh1;
                smw[N_ACT_L + wi + 8 * ASTR] = ll1;
            }
        }
        __syncwarp();

        uint32_t a2h[32], a2l[32];
        {
            const int r0w = rowbase + qid;
#pragma unroll
            for (int kt = 0; kt < 8; kt++) {
                int b0 = r0w + kt * 8;
                a2h[kt * 4 + 0] = smw[N_ACT_H + b0];
                a2h[kt * 4 + 1] = smw[N_ACT_H + b0 + 8 * ASTR];
                a2h[kt * 4 + 2] = smw[N_ACT_H + b0 + 4];
                a2h[kt * 4 + 3] = smw[N_ACT_H + b0 + 8 * ASTR + 4];
                a2l[kt * 4 + 0] = smw[N_ACT_L + b0];
                a2l[kt * 4 + 1] = smw[N_ACT_L + b0 + 8 * ASTR];
                a2l[kt * 4 + 2] = smw[N_ACT_L + b0 + 4];
                a2l[kt * 4 + 3] = smw[N_ACT_L + b0 + 8 * ASTR + 4];
            }
        }
        const int r0 = tile * 128 + w * 16 + grp;
        const int r1 = r0 + 8;

#pragma unroll
        for (int nt = 0; nt < 8; nt++) {
            float c[4] = {0.f, 0.f, 0.f, 0.f};
            const int base = nt * 8 * WSTR + bq;
#pragma unroll
            for (int kt = 0; kt < 8; kt++) {
                int o = base + kt * 8;
                uint32_t bh0 = smw[N_W2_HI + o], bh1 = smw[N_W2_HI + o + 4];
                uint32_t bl0 = smw[N_W2_LO + o], bl1 = smw[N_W2_LO + o + 4];
                MMA_BF16(c, a2h[kt*4], a2h[kt*4+1], a2h[kt*4+2], a2h[kt*4+3], bh0, bh1);
                MMA_BF16(c, a2l[kt*4], a2l[kt*4+1], a2l[kt*4+2], a2l[kt*4+3], bh0, bh1);
                MMA_BF16(c, a2h[kt*4], a2h[kt*4+1], a2h[kt*4+2], a2h[kt*4+3], bl0, bl1);
            }
            int n0 = nt * 8 + 2 * qid;
            float b0v = __ldg(&bn2[n0]), b1v = __ldg(&bn2[n0 + 1]);
            if (r0 < N) {
                float2 o2 = make_float2(c[0] + b0v, c[1] + b1v);
                *(float2*)(out + (size_t)r0 * 64 + n0) = o2;
            }
            if (r1 < N) {
                float2 o2 = make_float2(c[2] + b0v, c[3] + b1v);
                *(float2*)(out + (size_t)r1 * 64 + n0) = o2;
            }
        }
        __syncthreads();
    }
}

// ===========================================================================
extern "C" void kernel_launch(void* const* d_in, const int* in_sizes, int n_in,
                              void* d_out, int out_size) {
    const float* z_h       = (const float*)d_in[0];
    const float* pos_world = (const float*)d_in[1];
    const int*   ei        = (const int*)d_in[2];
    const float* We1 = (const float*)d_in[3];
    const float* be1 = (const float*)d_in[4];
    const float* We2 = (const float*)d_in[5];
    const float* be2 = (const float*)d_in[6];
    const float* Wg1 = (const float*)d_in[7];
    const float* bg1 = (const float*)d_in[8];
    const float* Wg2 = (const float*)d_in[9];
    const float* bg2 = (const float*)d_in[10];
    const float* Wn1 = (const float*)d_in[11];
    const float* bn1 = (const float*)d_in[12];
    const float* Wn2 = (const float*)d_in[13];
    const float* bn2 = (const float*)d_in[14];
    const float* Ww1 = (const float*)d_in[15];
    const float* bw1 = (const float*)d_in[16];
    const float* Ww2 = (const float*)d_in[17];
    const float* bw2 = (const float*)d_in[18];

    const int N = in_sizes[0] / 64;
    const int E = in_sizes[2] / 2;
    float* out = (float*)d_out;

    cudaFuncSetAttribute(edge_mma_kernel,
                         cudaFuncAttributeMaxDynamicSharedMemorySize, E_BYTES);
    cudaFuncSetAttribute(node_mma_kernel,
                         cudaFuncAttributeMaxDynamicSharedMemorySize, N_BYTES);
    cudaFuncSetAttribute(world_mma_kernel,
                         cudaFuncAttributeMaxDynamicSharedMemorySize, W_BYTES);

    const int NWB = 148;
    world_mma_kernel<<<NWB, 256, W_BYTES>>>(z_h, pos_world, Ww1, bw1, Ww2, N);
    edge_mma_kernel<<<148, ETHREADS, E_BYTES>>>(ei, We1, be1, We2, be2,
                                                Wg1, bg1, Wg2, bg2, E);
    node_mma_kernel<<<148, 256, N_BYTES>>>(z_h, Wn1, bn1, Wn2, bn2, bw2,
                                           out, N, NWB);
}